// round 4
// baseline (speedup 1.0000x reference)
#include <cuda_runtime.h>
#include <math.h>

// Problem constants (fixed by the dataset):
//   feat     [2,128,64,64]
//   coord    [2,65536,2]
//   hr_guide [2,128,256,256]
//   lr_guide [2,128,64,64]
//   MLP: 386 -> 1024 -> 512 -> 256 -> 128 -> 2
// We process the 4 neighbor-offsets as 4 sequential passes of M = B*N = 131072 rows.

#define M_ROWS 131072           // B * N  (= 2^17)
#define K1 386
#define N1 1024
#define N2 512
#define N3 256
#define N4 128

// ---------- scratch (device globals; allocation-free per harness rules) ----------
__device__ float g_INP[(size_t)K1 * M_ROWS];   // [K][M] feature-major
__device__ float g_X1 [(size_t)N1 * M_ROWS];
__device__ float g_X2 [(size_t)N2 * M_ROWS];
__device__ float g_X3 [(size_t)N3 * M_ROWS];
__device__ float g_X4 [(size_t)N4 * M_ROWS];
__device__ float g_P0 [4 * M_ROWS];
__device__ float g_P1 [4 * M_ROWS];
__device__ int   g_ihr [M_ROWS];
__device__ int   g_ilr [M_ROWS];
__device__ float g_rely[M_ROWS];
__device__ float g_relx[M_ROWS];

__device__ __forceinline__ float* get_buf(int id) {
    switch (id) {
        case 0:  return g_INP;
        case 1:  return g_X1;
        case 2:  return g_X2;
        case 3:  return g_X3;
        default: return g_X4;
    }
}

// ---------- meta: per-row nearest-sample indices + rel_coord ----------
// Replicates: fy = (g+1)*H/2 - 0.5 ; i = floor(fy + 0.5) ; valid in-range ; clip.
__global__ void meta_kernel(const float* __restrict__ coord, float vx, float vy) {
    int m = blockIdx.x * blockDim.x + threadIdx.x;
    if (m >= M_ROWS) return;
    float cy0 = coord[2 * m + 0];
    float cx0 = coord[2 * m + 1];

    // HR (256x256) sample at (cy0, cx0)
    {
        float fy = (cy0 + 1.0f) * 256.0f / 2.0f - 0.5f;
        float fx = (cx0 + 1.0f) * 256.0f / 2.0f - 0.5f;
        int iy = (int)floorf(fy + 0.5f);
        int ix = (int)floorf(fx + 0.5f);
        bool v = (iy >= 0) && (iy < 256) && (ix >= 0) && (ix < 256);
        int iyc = min(max(iy, 0), 255);
        int ixc = min(max(ix, 0), 255);
        g_ihr[m] = v ? (iyc * 256 + ixc) : -1;
    }

    // LR (64x64) sample at offset coordinate
    {
        float cy = cy0 + vx * (1.0f / 64.0f);
        float cx = cx0 + vy * (1.0f / 64.0f);
        float fy = (cy + 1.0f) * 64.0f / 2.0f - 0.5f;
        float fx = (cx + 1.0f) * 64.0f / 2.0f - 0.5f;
        int iy = (int)floorf(fy + 0.5f);
        int ix = (int)floorf(fx + 0.5f);
        bool v = (iy >= 0) && (iy < 64) && (ix >= 0) && (ix < 64);
        int iyc = min(max(iy, 0), 63);
        int ixc = min(max(ix, 0), 63);
        g_ilr[m] = v ? (iyc * 64 + ixc) : -1;
        const float rh = 1.0f / 64.0f;
        // feat_coord value at sampled cell (zeroed when invalid, like reference)
        float qy = v ? (-1.0f + rh + 2.0f * rh * (float)iyc) : 0.0f;
        float qx = v ? (-1.0f + rh + 2.0f * rh * (float)ixc) : 0.0f;
        g_rely[m] = (cy0 - qy) * 64.0f;
        g_relx[m] = (cx0 - qx) * 64.0f;
    }
}

// ---------- fill INP [K=386][M] feature-major ----------
// thread id = k*M + m : consecutive threads -> consecutive pixels -> coalesced
// gathers (ix advances with n) AND coalesced scratch writes.
__global__ void fill_inp_kernel(const float* __restrict__ feat,
                                const float* __restrict__ hr,
                                const float* __restrict__ lr) {
    size_t tid = (size_t)blockIdx.x * blockDim.x + threadIdx.x;
    if (tid >= (size_t)K1 * M_ROWS) return;
    int k = (int)(tid >> 17);          // / M_ROWS
    int m = (int)(tid & (M_ROWS - 1)); // % M_ROWS
    int b = m >> 16;                   // batch (N = 65536)

    float val;
    if (k < 128) {                     // q_feat
        int il = g_ilr[m];
        val = (il >= 0) ? feat[(size_t)(b * 128 + k) * 4096 + il] : 0.0f;
    } else if (k < 256) {              // q_guide_hr
        int ih = g_ihr[m];
        val = (ih >= 0) ? hr[(size_t)(b * 128 + (k - 128)) * 65536 + ih] : 0.0f;
    } else if (k < 384) {              // q_guide_hr - q_guide_lr
        int c = k - 256;
        int ih = g_ihr[m];
        int il = g_ilr[m];
        float a  = (ih >= 0) ? hr[(size_t)(b * 128 + c) * 65536 + ih] : 0.0f;
        float bb = (il >= 0) ? lr[(size_t)(b * 128 + c) * 4096  + il] : 0.0f;
        val = a - bb;
    } else if (k == 384) {
        val = g_rely[m];
    } else {
        val = g_relx[m];
    }
    g_INP[tid] = val;
}

// ---------- fp32 GEMM, feature-major activations ----------
// C[n][m] = relu_opt( sum_k W[k][n] * A[k][m] + bias[n] )
// A: [K][M] (lda = M_ROWS), W: [K][Nn] row-major, C: [Nn][M].
// Tiles: BM=128 (m), BN=128 (n), BK=8; 256 threads; 8x8 register microtiles.
__global__ __launch_bounds__(256, 2)
void gemm_cm(int a_id, const float* __restrict__ W, const float* __restrict__ bias,
             int c_id, int Nn, int K, int relu) {
    const float* __restrict__ A = get_buf(a_id);
    float* __restrict__ C = get_buf(c_id);

    __shared__ float As[8][128];
    __shared__ float Ws[8][128];

    int m0 = blockIdx.x * 128;
    int n0 = blockIdx.y * 128;
    int tid = threadIdx.x;
    int lk = tid >> 5;          // 0..7 : k row within tile
    int lv = (tid & 31) << 2;   // 0..124 step 4 : vector position
    int tx = tid & 15;          // m microtile group
    int ty = tid >> 4;          // n microtile group

    float acc[8][8];            // [n][m]
#pragma unroll
    for (int j = 0; j < 8; j++)
#pragma unroll
        for (int i = 0; i < 8; i++) acc[j][i] = 0.0f;

    for (int k0 = 0; k0 < K; k0 += 8) {
        int kk = k0 + lk;
        float4 av, wv;
        if (kk < K) {
            av = *(const float4*)&A[(size_t)kk * M_ROWS + m0 + lv];
            wv = *(const float4*)&W[(size_t)kk * Nn + n0 + lv];
        } else {
            av = make_float4(0.f, 0.f, 0.f, 0.f);
            wv = av;
        }
        __syncthreads();
        *(float4*)&As[lk][lv] = av;
        *(float4*)&Ws[lk][lv] = wv;
        __syncthreads();

#pragma unroll
        for (int k = 0; k < 8; k++) {
            float a[8], w[8];
            *(float4*)&a[0] = *(const float4*)&As[k][tx * 8];
            *(float4*)&a[4] = *(const float4*)&As[k][tx * 8 + 4];
            *(float4*)&w[0] = *(const float4*)&Ws[k][ty * 8];
            *(float4*)&w[4] = *(const float4*)&Ws[k][ty * 8 + 4];
#pragma unroll
            for (int j = 0; j < 8; j++)
#pragma unroll
                for (int i = 0; i < 8; i++)
                    acc[j][i] += w[j] * a[i];
        }
    }

#pragma unroll
    for (int j = 0; j < 8; j++) {
        int n = n0 + ty * 8 + j;
        float bb = bias[n];
        float4 o0, o1;
        float* op0 = (float*)&o0;
        float* op1 = (float*)&o1;
#pragma unroll
        for (int i = 0; i < 4; i++) {
            float v = acc[j][i] + bb;
            op0[i] = relu ? fmaxf(v, 0.0f) : v;
        }
#pragma unroll
        for (int i = 0; i < 4; i++) {
            float v = acc[j][i + 4] + bb;
            op1[i] = relu ? fmaxf(v, 0.0f) : v;
        }
        *(float4*)&C[(size_t)n * M_ROWS + m0 + tx * 8]     = o0;
        *(float4*)&C[(size_t)n * M_ROWS + m0 + tx * 8 + 4] = o1;
    }
}

// ---------- layer 5: [M,128] @ [128,2] + b5 ----------
__global__ void layer5_kernel(const float* __restrict__ w5,
                              const float* __restrict__ b5, int o) {
    __shared__ float ws0[128], ws1[128];
    int t = threadIdx.x;
    if (t < 128) {
        ws0[t] = w5[t * 2 + 0];
        ws1[t] = w5[t * 2 + 1];
    }
    __syncthreads();
    int m = blockIdx.x * blockDim.x + t;
    float a0 = b5[0], a1 = b5[1];
#pragma unroll 8
    for (int k = 0; k < 128; k++) {
        float a = g_X4[(size_t)k * M_ROWS + m];
        a0 += a * ws0[k];
        a1 += a * ws1[k];
    }
    g_P0[o * M_ROWS + m] = a0;
    g_P1[o * M_ROWS + m] = a1;
}

// ---------- softmax-weighted combine over the 4 offsets ----------
__global__ void combine_kernel(float* __restrict__ out) {
    int m = blockIdx.x * blockDim.x + threadIdx.x;
    if (m >= M_ROWS) return;
    float l0 = g_P1[0 * M_ROWS + m];
    float l1 = g_P1[1 * M_ROWS + m];
    float l2 = g_P1[2 * M_ROWS + m];
    float l3 = g_P1[3 * M_ROWS + m];
    float mx = fmaxf(fmaxf(l0, l1), fmaxf(l2, l3));
    float e0 = expf(l0 - mx), e1 = expf(l1 - mx), e2 = expf(l2 - mx), e3 = expf(l3 - mx);
    float s = e0 + e1 + e2 + e3;
    float r = (g_P0[0 * M_ROWS + m] * e0 + g_P0[1 * M_ROWS + m] * e1 +
               g_P0[2 * M_ROWS + m] * e2 + g_P0[3 * M_ROWS + m] * e3) / s;
    out[m] = r;
}

extern "C" void kernel_launch(void* const* d_in, const int* in_sizes, int n_in,
                              void* d_out, int out_size) {
    const float* feat  = (const float*)d_in[0];
    const float* coord = (const float*)d_in[1];
    const float* hr    = (const float*)d_in[2];
    const float* lr    = (const float*)d_in[3];
    const float* w1 = (const float*)d_in[4];  const float* b1 = (const float*)d_in[5];
    const float* w2 = (const float*)d_in[6];  const float* b2 = (const float*)d_in[7];
    const float* w3 = (const float*)d_in[8];  const float* b3 = (const float*)d_in[9];
    const float* w4 = (const float*)d_in[10]; const float* b4 = (const float*)d_in[11];
    const float* w5 = (const float*)d_in[12]; const float* b5 = (const float*)d_in[13];
    float* out = (float*)d_out;

    // offsets match reference loop order: vx in (-1,1) outer, vy in (-1,1) inner
    const float offs[4][2] = {{-1.f, -1.f}, {-1.f, 1.f}, {1.f, -1.f}, {1.f, 1.f}};

    for (int o = 0; o < 4; o++) {
        meta_kernel<<<M_ROWS / 256, 256>>>(coord, offs[o][0], offs[o][1]);
        fill_inp_kernel<<<(unsigned)((size_t)K1 * M_ROWS / 256), 256>>>(feat, hr, lr);

        dim3 g1(M_ROWS / 128, N1 / 128);
        gemm_cm<<<g1, 256>>>(0, w1, b1, 1, N1, K1, 1);
        dim3 g2(M_ROWS / 128, N2 / 128);
        gemm_cm<<<g2, 256>>>(1, w2, b2, 2, N2, N1, 1);
        dim3 g3(M_ROWS / 128, N3 / 128);
        gemm_cm<<<g3, 256>>>(2, w3, b3, 3, N3, N2, 1);
        dim3 g4(M_ROWS / 128, N4 / 128);
        gemm_cm<<<g4, 256>>>(3, w4, b4, 4, N4, N3, 1);

        layer5_kernel<<<M_ROWS / 256, 256>>>(w5, b5, o);
    }
    combine_kernel<<<M_ROWS / 256, 256>>>(out);
}

// round 6
// speedup vs baseline: 2.0310x; 2.0310x over previous
#include <cuda_runtime.h>
#include <cuda_bf16.h>
#include <math.h>
#include <stdint.h>

// Problem constants:
//   feat [2,128,64,64], coord [2,65536,2], hr_guide [2,128,256,256], lr_guide [2,128,64,64]
//   MLP: 386 -> 1024 -> 512 -> 256 -> 128 -> 2, 4 offset passes, M = B*N = 131072 rows.
// Engine: mma.sync bf16x3-split GEMMs (D = Ahi*Whi + Ahi*Wlo + Alo*Whi), fp32 accum in
// registers. Activations as (hi,lo) bf16 pairs, [M][Kpad] K-major. cp.async double-buffered
// SW128 staging, ldmatrix fragment loads. (tcgen05 unavailable: harness PTX target is
// compute_103, not compute_103a.)

#define MTOT 131072

#define KP1 448     // 386 padded to 7*64
#define KP2 1024
#define KP3 512
#define KP4 256
#define NO1 1024
#define NO2 512
#define NO3 256
#define NO4 128

// ---------------- scratch (device globals) ----------------
__device__ __nv_bfloat16 g_INPh[(size_t)MTOT * KP1];
__device__ __nv_bfloat16 g_INPl[(size_t)MTOT * KP1];
__device__ __nv_bfloat16 g_X1h[(size_t)MTOT * NO1];
__device__ __nv_bfloat16 g_X1l[(size_t)MTOT * NO1];
__device__ __nv_bfloat16 g_X2h[(size_t)MTOT * NO2];
__device__ __nv_bfloat16 g_X2l[(size_t)MTOT * NO2];
__device__ __nv_bfloat16 g_X3h[(size_t)MTOT * NO3];
__device__ __nv_bfloat16 g_X3l[(size_t)MTOT * NO3];
__device__ __nv_bfloat16 g_X4h[(size_t)MTOT * NO4];
__device__ __nv_bfloat16 g_X4l[(size_t)MTOT * NO4];

__device__ __nv_bfloat16 g_W1h[(size_t)NO1 * KP1];
__device__ __nv_bfloat16 g_W1l[(size_t)NO1 * KP1];
__device__ __nv_bfloat16 g_W2h[(size_t)NO2 * KP2];
__device__ __nv_bfloat16 g_W2l[(size_t)NO2 * KP2];
__device__ __nv_bfloat16 g_W3h[(size_t)NO3 * KP3];
__device__ __nv_bfloat16 g_W3l[(size_t)NO3 * KP3];
__device__ __nv_bfloat16 g_W4h[(size_t)NO4 * KP4];
__device__ __nv_bfloat16 g_W4l[(size_t)NO4 * KP4];

__device__ float g_P0[4 * MTOT];
__device__ float g_P1[4 * MTOT];
__device__ int   g_ihr[MTOT];
__device__ int   g_ilr[MTOT];
__device__ float g_rely[MTOT];
__device__ float g_relx[MTOT];

// ---------------- helpers ----------------
__device__ __forceinline__ uint32_t smem_u32(const void* p) {
    uint32_t a;
    asm("{ .reg .u64 t; cvta.to.shared.u64 t, %1; cvt.u32.u64 %0, t; }" : "=r"(a) : "l"(p));
    return a;
}

__device__ __forceinline__ uint32_t swz128(uint32_t off) {
    return off ^ ((off >> 3) & 0x70);
}

__device__ __forceinline__ void bf16_split(float v, __nv_bfloat16& h, __nv_bfloat16& l) {
    h = __float2bfloat16(v);
    l = __float2bfloat16(v - __bfloat162float(h));
}

#define LDSM4(r, addr) \
    asm volatile("ldmatrix.sync.aligned.m8n8.x4.shared.b16 {%0,%1,%2,%3}, [%4];" \
        : "=r"((r)[0]), "=r"((r)[1]), "=r"((r)[2]), "=r"((r)[3]) : "r"(addr))

#define MMA_BF16(dd, aa, b0, b1) \
    asm volatile("mma.sync.aligned.m16n8k16.row.col.f32.bf16.bf16.f32 " \
        "{%0,%1,%2,%3}, {%4,%5,%6,%7}, {%8,%9}, {%0,%1,%2,%3};" \
        : "+f"((dd)[0]), "+f"((dd)[1]), "+f"((dd)[2]), "+f"((dd)[3]) \
        : "r"((aa)[0]), "r"((aa)[1]), "r"((aa)[2]), "r"((aa)[3]), "r"(b0), "r"(b1))

#define CP_ASYNC16(sa, ga) \
    asm volatile("cp.async.cg.shared.global [%0], [%1], 16;" :: "r"(sa), "l"(ga) : "memory")

// ---------------- meta ----------------
__global__ void meta_kernel(const float* __restrict__ coord, float vx, float vy) {
    int m = blockIdx.x * blockDim.x + threadIdx.x;
    if (m >= MTOT) return;
    float cy0 = coord[2 * m + 0];
    float cx0 = coord[2 * m + 1];
    {
        float fy = (cy0 + 1.0f) * 128.0f - 0.5f;
        float fx = (cx0 + 1.0f) * 128.0f - 0.5f;
        int iy = (int)floorf(fy + 0.5f);
        int ix = (int)floorf(fx + 0.5f);
        bool v = (iy >= 0) && (iy < 256) && (ix >= 0) && (ix < 256);
        int iyc = min(max(iy, 0), 255);
        int ixc = min(max(ix, 0), 255);
        g_ihr[m] = v ? (iyc * 256 + ixc) : -1;
    }
    {
        float cy = cy0 + vx * (1.0f / 64.0f);
        float cx = cx0 + vy * (1.0f / 64.0f);
        float fy = (cy + 1.0f) * 32.0f - 0.5f;
        float fx = (cx + 1.0f) * 32.0f - 0.5f;
        int iy = (int)floorf(fy + 0.5f);
        int ix = (int)floorf(fx + 0.5f);
        bool v = (iy >= 0) && (iy < 64) && (ix >= 0) && (ix < 64);
        int iyc = min(max(iy, 0), 63);
        int ixc = min(max(ix, 0), 63);
        g_ilr[m] = v ? (iyc * 64 + ixc) : -1;
        const float rh = 1.0f / 64.0f;
        float qy = v ? (-1.0f + rh + 2.0f * rh * (float)iyc) : 0.0f;
        float qx = v ? (-1.0f + rh + 2.0f * rh * (float)ixc) : 0.0f;
        g_rely[m] = (cy0 - qy) * 64.0f;
        g_relx[m] = (cx0 - qx) * 64.0f;
    }
}

// ---------------- weight prep: W[k][n] fp32 -> Wh/Wl [n][Kpad] bf16 ----------------
__global__ void prep_w_kernel(const float* __restrict__ W, int layer) {
    __nv_bfloat16 *Wh, *Wl;
    int K, Kpad, N;
    switch (layer) {
        case 1: Wh = g_W1h; Wl = g_W1l; K = 386;  Kpad = KP1; N = NO1; break;
        case 2: Wh = g_W2h; Wl = g_W2l; K = 1024; Kpad = KP2; N = NO2; break;
        case 3: Wh = g_W3h; Wl = g_W3l; K = 512;  Kpad = KP3; N = NO3; break;
        default:Wh = g_W4h; Wl = g_W4l; K = 256;  Kpad = KP4; N = NO4; break;
    }
    size_t idx = (size_t)blockIdx.x * blockDim.x + threadIdx.x;
    if (idx >= (size_t)N * Kpad) return;
    int n = (int)(idx / Kpad);
    int k = (int)(idx % Kpad);
    float v = (k < K) ? W[(size_t)k * N + n] : 0.0f;
    __nv_bfloat16 h, l;
    bf16_split(v, h, l);
    Wh[idx] = h;
    Wl[idx] = l;
}

// ---------------- fill INP [m][448] hi/lo with SMEM transpose ----------------
__global__ __launch_bounds__(256) void fill_inp_kernel(const float* __restrict__ feat,
                                                       const float* __restrict__ hr,
                                                       const float* __restrict__ lr) {
    __shared__ float vals[KP1][17];
    __shared__ int   s_ihr[16], s_ilr[16];
    __shared__ float s_ry[16], s_rx[16];
    int t = threadIdx.x;
    int m0 = blockIdx.x * 16;
    if (t < 16) {
        int m = m0 + t;
        s_ihr[t] = g_ihr[m];
        s_ilr[t] = g_ilr[m];
        s_ry[t]  = g_rely[m];
        s_rx[t]  = g_relx[m];
    }
    __syncthreads();

    int ml = t & 15;
    int kb = t >> 4;
    int m  = m0 + ml;
    int b  = m >> 16;
    int ih = s_ihr[ml];
    int il = s_ilr[ml];
#pragma unroll 4
    for (int kk = 0; kk < KP1; kk += 16) {
        int k = kk + kb;
        float val;
        if (k < 128) {
            val = (il >= 0) ? feat[(size_t)(b * 128 + k) * 4096 + il] : 0.0f;
        } else if (k < 256) {
            val = (ih >= 0) ? hr[(size_t)(b * 128 + (k - 128)) * 65536 + ih] : 0.0f;
        } else if (k < 384) {
            int c = k - 256;
            float a  = (ih >= 0) ? hr[(size_t)(b * 128 + c) * 65536 + ih] : 0.0f;
            float bb = (il >= 0) ? lr[(size_t)(b * 128 + c) * 4096  + il] : 0.0f;
            val = a - bb;
        } else if (k == 384) {
            val = s_ry[ml];
        } else if (k == 385) {
            val = s_rx[ml];
        } else {
            val = 0.0f;
        }
        vals[k][ml] = val;
    }
    __syncthreads();

    int mw = t >> 6;
    int kw = t & 63;
#pragma unroll
    for (int mi = 0; mi < 4; mi++) {
        int mm = mi * 4 + mw;
        size_t base = (size_t)(m0 + mm) * KP1;
#pragma unroll
        for (int ki = 0; ki < 7; ki++) {
            int k = ki * 64 + kw;
            float v = vals[k][mm];
            __nv_bfloat16 h, l;
            bf16_split(v, h, l);
            g_INPh[base + k] = h;
            g_INPl[base + k] = l;
        }
    }
}

// ---------------- mma.sync GEMM ----------------
// out[m][n] = relu(sum_k A[m][k] * W[n][k] + bias[n]); bf16x3 split, fp32 acc in regs.
// CTA tile 128m x 128n, 8 warps (2m x 4n), warp tile 64m x 32n.
// K chunks of 64 (128B SW128 rows). Stage = 4 tiles x 16KB = 64KB, double buffered.
#define TILE_BYTES 16384
#define STAGE_BYTES (4 * TILE_BYTES)
#define GEMM_SMEM   (2 * STAGE_BYTES + 1024)

__global__ __launch_bounds__(256) void gemm_mma(int layer, const float* __restrict__ bias) {
    const __nv_bfloat16 *Ah, *Al, *Wh, *Wl;
    __nv_bfloat16 *Oh, *Ol;
    int Kpad, Nout;
    switch (layer) {
        case 1: Ah = g_INPh; Al = g_INPl; Wh = g_W1h; Wl = g_W1l; Oh = g_X1h; Ol = g_X1l; Kpad = KP1; Nout = NO1; break;
        case 2: Ah = g_X1h;  Al = g_X1l;  Wh = g_W2h; Wl = g_W2l; Oh = g_X2h; Ol = g_X2l; Kpad = KP2; Nout = NO2; break;
        case 3: Ah = g_X2h;  Al = g_X2l;  Wh = g_W3h; Wl = g_W3l; Oh = g_X3h; Ol = g_X3l; Kpad = KP3; Nout = NO3; break;
        default:Ah = g_X3h;  Al = g_X3l;  Wh = g_W4h; Wl = g_W4l; Oh = g_X4h; Ol = g_X4l; Kpad = KP4; Nout = NO4; break;
    }

    extern __shared__ char dsm[];
    __shared__ float s_bias[128];

    int tid = threadIdx.x;
    int wid = tid >> 5;
    int lane = tid & 31;
    int warp_m = wid >> 2;      // 0..1
    int warp_n = wid & 3;       // 0..3
    int n0 = blockIdx.x * 128;
    int m0 = blockIdx.y * 128;

    uint32_t dyn = (smem_u32(dsm) + 1023u) & ~1023u;
    if (tid < 128) s_bias[tid] = bias[n0 + tid];

    const int NC = Kpad >> 6;

    float acc[4][4][4];
#pragma unroll
    for (int i = 0; i < 4; i++)
#pragma unroll
        for (int j = 0; j < 4; j++)
#pragma unroll
            for (int r = 0; r < 4; r++) acc[i][j][r] = 0.0f;

    // ldmatrix per-thread address components (within a 128row x 128B tile):
    // A: m-tile i: row = warp_m*64 + i*16 + (lane&15), byte col = ks*32 + (lane>>4)*16
    // W (x4 over 2 n-tiles): j2: row = warp_n*32 + j2*16 + ((lane>>4)<<3) + (lane&7),
    //                        byte col = ks*32 + ((lane>>3)&1)*16
    // swz128(row*128 + bc) = row*128 + (bc ^ ((row&7)<<4))   [bc < 128]
    uint32_t a_off[4], a_xor[4];
#pragma unroll
    for (int i = 0; i < 4; i++) {
        uint32_t row = warp_m * 64 + i * 16 + (lane & 15);
        a_off[i] = row << 7;
        a_xor[i] = (row & 7) << 4;
    }
    uint32_t w_off[2], w_xor[2];
#pragma unroll
    for (int j2 = 0; j2 < 2; j2++) {
        uint32_t row = warp_n * 32 + j2 * 16 + ((lane >> 4) << 3) + (lane & 7);
        w_off[j2] = row << 7;
        w_xor[j2] = (row & 7) << 4;
    }
    uint32_t a_hi16 = (lane >> 4) << 4;       // 0 or 16
    uint32_t w_hi16 = ((lane >> 3) & 1) << 4; // 0 or 16

    // loader: 4 tiles (Ahi, Alo, Whi, Wlo), 16 cp.async x 16B per thread
    auto issue_loads = [&](int c) {
        uint32_t sb = dyn + (c & 1) * STAGE_BYTES;
        int k0 = c << 6;
#pragma unroll
        for (int it = 0; it < 16; it++) {
            int tile = it >> 2;
            int c2 = ((it & 3) << 8) + tid;
            int row = c2 >> 3;
            int col = c2 & 7;
            const __nv_bfloat16* src;
            size_t gidx;
            if (tile < 2) {
                src = (tile == 0) ? Ah : Al;
                gidx = (size_t)(m0 + row) * Kpad + k0 + col * 8;
            } else {
                src = (tile == 2) ? Wh : Wl;
                gidx = (size_t)(n0 + row) * Kpad + k0 + col * 8;
            }
            uint32_t sa = sb + tile * TILE_BYTES + swz128((row << 7) + (col << 4));
            CP_ASYNC16(sa, __cvta_generic_to_global(src + gidx));
        }
        asm volatile("cp.async.commit_group;" ::: "memory");
    };

    issue_loads(0);

    for (int c = 0; c < NC; c++) {
        if (c + 1 < NC) {
            issue_loads(c + 1);
            asm volatile("cp.async.wait_group 1;" ::: "memory");
        } else {
            asm volatile("cp.async.wait_group 0;" ::: "memory");
        }
        __syncthreads();

        uint32_t sb  = dyn + (c & 1) * STAGE_BYTES;
        uint32_t bAh = sb;
        uint32_t bAl = sb + TILE_BYTES;
        uint32_t bWh = sb + 2 * TILE_BYTES;
        uint32_t bWl = sb + 3 * TILE_BYTES;

#pragma unroll
        for (int ks = 0; ks < 4; ks++) {
            uint32_t bcA = (uint32_t)(ks * 32) + a_hi16;
            uint32_t bcW = (uint32_t)(ks * 32) + w_hi16;

            uint32_t ahi[4][4], alo[4][4];
#pragma unroll
            for (int i = 0; i < 4; i++) {
                uint32_t o = a_off[i] + (bcA ^ a_xor[i]);
                LDSM4(ahi[i], bAh + o);
                LDSM4(alo[i], bAl + o);
            }
            uint32_t bhi[2][4], blo[2][4];
#pragma unroll
            for (int j2 = 0; j2 < 2; j2++) {
                uint32_t o = w_off[j2] + (bcW ^ w_xor[j2]);
                LDSM4(bhi[j2], bWh + o);
                LDSM4(blo[j2], bWl + o);
            }
            // bhi[j2] regs: {b0(ntile 2*j2), b1(ntile 2*j2), b0(2*j2+1), b1(2*j2+1)}
#pragma unroll
            for (int i = 0; i < 4; i++) {
#pragma unroll
                for (int j = 0; j < 4; j++) {
                    int j2 = j >> 1, jh = (j & 1) << 1;
                    MMA_BF16(acc[i][j], ahi[i], bhi[j2][jh], bhi[j2][jh + 1]);
                    MMA_BF16(acc[i][j], ahi[i], blo[j2][jh], blo[j2][jh + 1]);
                    MMA_BF16(acc[i][j], alo[i], bhi[j2][jh], bhi[j2][jh + 1]);
                }
            }
        }
        __syncthreads();
    }

    // epilogue: bias + relu + bf16 hi/lo split
    int q = lane >> 2, p = lane & 3;
#pragma unroll
    for (int i = 0; i < 4; i++) {
        int r0 = m0 + warp_m * 64 + i * 16 + q;
        size_t o0 = (size_t)r0 * Nout + n0;
        size_t o1 = (size_t)(r0 + 8) * Nout + n0;
#pragma unroll
        for (int j = 0; j < 4; j++) {
            int nn = warp_n * 32 + j * 8 + p * 2;
            float bb0 = s_bias[nn], bb1 = s_bias[nn + 1];
            float v00 = fmaxf(acc[i][j][0] + bb0, 0.0f);
            float v01 = fmaxf(acc[i][j][1] + bb1, 0.0f);
            float v10 = fmaxf(acc[i][j][2] + bb0, 0.0f);
            float v11 = fmaxf(acc[i][j][3] + bb1, 0.0f);
            __nv_bfloat16 h00, l00, h01, l01, h10, l10, h11, l11;
            bf16_split(v00, h00, l00);
            bf16_split(v01, h01, l01);
            bf16_split(v10, h10, l10);
            bf16_split(v11, h11, l11);
            *(__nv_bfloat162*)(Oh + o0 + nn) = __nv_bfloat162(h00, h01);
            *(__nv_bfloat162*)(Ol + o0 + nn) = __nv_bfloat162(l00, l01);
            *(__nv_bfloat162*)(Oh + o1 + nn) = __nv_bfloat162(h10, h11);
            *(__nv_bfloat162*)(Ol + o1 + nn) = __nv_bfloat162(l10, l11);
        }
    }
}

// ---------------- layer 5: warp per pixel, X4 = hi+lo ----------------
__global__ __launch_bounds__(256) void layer5_kernel(const float* __restrict__ w5,
                                                     const float* __restrict__ b5, int o) {
    __shared__ float ws0[128], ws1[128];
    int t = threadIdx.x;
    if (t < 128) {
        ws0[t] = w5[t * 2 + 0];
        ws1[t] = w5[t * 2 + 1];
    }
    __syncthreads();
    int m = blockIdx.x * 8 + (t >> 5);
    int lane = t & 31;
    size_t base = (size_t)m * 128 + lane * 4;
    __nv_bfloat162 h01 = *(const __nv_bfloat162*)(g_X4h + base);
    __nv_bfloat162 h23 = *(const __nv_bfloat162*)(g_X4h + base + 2);
    __nv_bfloat162 l01 = *(const __nv_bfloat162*)(g_X4l + base);
    __nv_bfloat162 l23 = *(const __nv_bfloat162*)(g_X4l + base + 2);
    float x0 = __bfloat162float(h01.x) + __bfloat162float(l01.x);
    float x1 = __bfloat162float(h01.y) + __bfloat162float(l01.y);
    float x2 = __bfloat162float(h23.x) + __bfloat162float(l23.x);
    float x3 = __bfloat162float(h23.y) + __bfloat162float(l23.y);
    int k = lane * 4;
    float a0 = x0 * ws0[k] + x1 * ws0[k + 1] + x2 * ws0[k + 2] + x3 * ws0[k + 3];
    float a1 = x0 * ws1[k] + x1 * ws1[k + 1] + x2 * ws1[k + 2] + x3 * ws1[k + 3];
#pragma unroll
    for (int s = 16; s > 0; s >>= 1) {
        a0 += __shfl_xor_sync(0xFFFFFFFF, a0, s);
        a1 += __shfl_xor_sync(0xFFFFFFFF, a1, s);
    }
    if (lane == 0) {
        g_P0[o * MTOT + m] = a0 + b5[0];
        g_P1[o * MTOT + m] = a1 + b5[1];
    }
}

// ---------------- softmax combine ----------------
__global__ void combine_kernel(float* __restrict__ out) {
    int m = blockIdx.x * blockDim.x + threadIdx.x;
    if (m >= MTOT) return;
    float l0 = g_P1[0 * MTOT + m];
    float l1 = g_P1[1 * MTOT + m];
    float l2 = g_P1[2 * MTOT + m];
    float l3 = g_P1[3 * MTOT + m];
    float mx = fmaxf(fmaxf(l0, l1), fmaxf(l2, l3));
    float e0 = expf(l0 - mx), e1 = expf(l1 - mx), e2 = expf(l2 - mx), e3 = expf(l3 - mx);
    float s = e0 + e1 + e2 + e3;
    float r = (g_P0[0 * MTOT + m] * e0 + g_P0[1 * MTOT + m] * e1 +
               g_P0[2 * MTOT + m] * e2 + g_P0[3 * MTOT + m] * e3) / s;
    out[m] = r;
}

extern "C" void kernel_launch(void* const* d_in, const int* in_sizes, int n_in,
                              void* d_out, int out_size) {
    const float* feat  = (const float*)d_in[0];
    const float* coord = (const float*)d_in[1];
    const float* hr    = (const float*)d_in[2];
    const float* lr    = (const float*)d_in[3];
    const float* w1 = (const float*)d_in[4];  const float* b1 = (const float*)d_in[5];
    const float* w2 = (const float*)d_in[6];  const float* b2 = (const float*)d_in[7];
    const float* w3 = (const float*)d_in[8];  const float* b3 = (const float*)d_in[9];
    const float* w4 = (const float*)d_in[10]; const float* b4 = (const float*)d_in[11];
    const float* w5 = (const float*)d_in[12]; const float* b5 = (const float*)d_in[13];
    float* out = (float*)d_out;

    cudaFuncSetAttribute(gemm_mma, cudaFuncAttributeMaxDynamicSharedMemorySize, GEMM_SMEM);

    prep_w_kernel<<<(unsigned)(((size_t)NO1 * KP1 + 255) / 256), 256>>>(w1, 1);
    prep_w_kernel<<<(unsigned)(((size_t)NO2 * KP2 + 255) / 256), 256>>>(w2, 2);
    prep_w_kernel<<<(unsigned)(((size_t)NO3 * KP3 + 255) / 256), 256>>>(w3, 3);
    prep_w_kernel<<<(unsigned)(((size_t)NO4 * KP4 + 255) / 256), 256>>>(w4, 4);

    const float offs[4][2] = {{-1.f, -1.f}, {-1.f, 1.f}, {1.f, -1.f}, {1.f, 1.f}};

    for (int o = 0; o < 4; o++) {
        meta_kernel<<<MTOT / 256, 256>>>(coord, offs[o][0], offs[o][1]);
        fill_inp_kernel<<<MTOT / 16, 256>>>(feat, hr, lr);

        // n-tile-fast grid so concurrent CTAs share A tiles via L2
        gemm_mma<<<dim3(NO1 / 128, MTOT / 128), 256, GEMM_SMEM>>>(1, b1);
        gemm_mma<<<dim3(NO2 / 128, MTOT / 128), 256, GEMM_SMEM>>>(2, b2);
        gemm_mma<<<dim3(NO3 / 128, MTOT / 128), 256, GEMM_SMEM>>>(3, b3);
        gemm_mma<<<dim3(NO4 / 128, MTOT / 128), 256, GEMM_SMEM>>>(4, b4);

        layer5_kernel<<<MTOT / 8, 256>>>(w5, b5, o);
    }
    combine_kernel<<<MTOT / 256, 256>>>(out);
}

// round 8
// speedup vs baseline: 4.5374x; 2.2340x over previous
#include <cuda_runtime.h>
#include <cuda_bf16.h>
#include <math.h>
#include <stdint.h>

// JIIF: feat [2,128,64,64], coord [2,65536,2], hr_guide [2,128,256,256], lr_guide [2,128,64,64]
// MLP 386->1024->512->256->128->2, 4 offset passes, M = 131072.
//
// Engine: mma.sync bf16x3-split GEMMs (D = Ahi*Whi + Ahi*Wlo + Alo*Whi), fp32 reg accum.
// Layer-1 decomposition:
//   inp@W1 = q_hr@(W_b+W_c)   [YHR: per-pixel, OFFSET-INDEPENDENT -> computed once]
//          + (q_feat@W_a - q_lr@W_c) [Z: per LR cell, only 8192 rows -> negligible]
//          + rel@W_d                  [2 FMAs in the assembly kernel]
// Per pass: X1 = relu(YHR + gather(Z, il) + rel@W_d + b1), then layers 2-4 GEMMs.

#define MTOT 131072
#define NCELL 8192              // B * 64*64

#define KH  128                 // q_hr channels (YHR GEMM K)
#define KC  256                 // cell GEMM K (feat 128 | lr 128)
#define KP2 1024
#define KP3 512
#define KP4 256
#define NO1 1024
#define NO2 512
#define NO3 256
#define NO4 128

// ---------------- scratch ----------------
__device__ __nv_bfloat16 g_QHRh[(size_t)MTOT * KH];
__device__ __nv_bfloat16 g_QHRl[(size_t)MTOT * KH];
__device__ __nv_bfloat16 g_CELLh[(size_t)NCELL * KC];
__device__ __nv_bfloat16 g_CELLl[(size_t)NCELL * KC];
__device__ float g_YHR[(size_t)MTOT * NO1];
__device__ float g_Z[(size_t)NCELL * NO1];

__device__ __nv_bfloat16 g_X1h[(size_t)MTOT * NO1];
__device__ __nv_bfloat16 g_X1l[(size_t)MTOT * NO1];
__device__ __nv_bfloat16 g_X2h[(size_t)MTOT * NO2];
__device__ __nv_bfloat16 g_X2l[(size_t)MTOT * NO2];
__device__ __nv_bfloat16 g_X3h[(size_t)MTOT * NO3];
__device__ __nv_bfloat16 g_X3l[(size_t)MTOT * NO3];
__device__ __nv_bfloat16 g_X4h[(size_t)MTOT * NO4];
__device__ __nv_bfloat16 g_X4l[(size_t)MTOT * NO4];

__device__ __nv_bfloat16 g_WHRh[(size_t)NO1 * KH];
__device__ __nv_bfloat16 g_WHRl[(size_t)NO1 * KH];
__device__ __nv_bfloat16 g_WCh[(size_t)NO1 * KC];
__device__ __nv_bfloat16 g_WCl[(size_t)NO1 * KC];
__device__ __nv_bfloat16 g_W2h[(size_t)NO2 * KP2];
__device__ __nv_bfloat16 g_W2l[(size_t)NO2 * KP2];
__device__ __nv_bfloat16 g_W3h[(size_t)NO3 * KP3];
__device__ __nv_bfloat16 g_W3l[(size_t)NO3 * KP3];
__device__ __nv_bfloat16 g_W4h[(size_t)NO4 * KP4];
__device__ __nv_bfloat16 g_W4l[(size_t)NO4 * KP4];

__device__ float g_P0[4 * MTOT];
__device__ float g_P1[4 * MTOT];
__device__ int   g_ihr[MTOT];
__device__ int   g_ilr[MTOT];
__device__ float g_rely[MTOT];
__device__ float g_relx[MTOT];

// ---------------- helpers ----------------
__device__ __forceinline__ uint32_t smem_u32(const void* p) {
    uint32_t a;
    asm("{ .reg .u64 t; cvta.to.shared.u64 t, %1; cvt.u32.u64 %0, t; }" : "=r"(a) : "l"(p));
    return a;
}
__device__ __forceinline__ uint32_t swz128(uint32_t off) {
    return off ^ ((off >> 3) & 0x70);
}
__device__ __forceinline__ void bf16_split(float v, __nv_bfloat16& h, __nv_bfloat16& l) {
    h = __float2bfloat16(v);
    l = __float2bfloat16(v - __bfloat162float(h));
}

#define LDSM4(r, addr) \
    asm volatile("ldmatrix.sync.aligned.m8n8.x4.shared.b16 {%0,%1,%2,%3}, [%4];" \
        : "=r"((r)[0]), "=r"((r)[1]), "=r"((r)[2]), "=r"((r)[3]) : "r"(addr))

#define MMA_BF16(dd, aa, b0, b1) \
    asm volatile("mma.sync.aligned.m16n8k16.row.col.f32.bf16.bf16.f32 " \
        "{%0,%1,%2,%3}, {%4,%5,%6,%7}, {%8,%9}, {%0,%1,%2,%3};" \
        : "+f"((dd)[0]), "+f"((dd)[1]), "+f"((dd)[2]), "+f"((dd)[3]) \
        : "r"((aa)[0]), "r"((aa)[1]), "r"((aa)[2]), "r"((aa)[3]), "r"(b0), "r"(b1))

#define CP_ASYNC16(sa, ga) \
    asm volatile("cp.async.cg.shared.global [%0], [%1], 16;" :: "r"(sa), "l"(ga) : "memory")

// ---------------- meta ----------------
__global__ void meta_kernel(const float* __restrict__ coord, float vx, float vy) {
    int m = blockIdx.x * blockDim.x + threadIdx.x;
    if (m >= MTOT) return;
    float cy0 = coord[2 * m + 0];
    float cx0 = coord[2 * m + 1];
    {
        float fy = (cy0 + 1.0f) * 128.0f - 0.5f;
        float fx = (cx0 + 1.0f) * 128.0f - 0.5f;
        int iy = (int)floorf(fy + 0.5f);
        int ix = (int)floorf(fx + 0.5f);
        bool v = (iy >= 0) && (iy < 256) && (ix >= 0) && (ix < 256);
        int iyc = min(max(iy, 0), 255);
        int ixc = min(max(ix, 0), 255);
        g_ihr[m] = v ? (iyc * 256 + ixc) : -1;
    }
    {
        float cy = cy0 + vx * (1.0f / 64.0f);
        float cx = cx0 + vy * (1.0f / 64.0f);
        float fy = (cy + 1.0f) * 32.0f - 0.5f;
        float fx = (cx + 1.0f) * 32.0f - 0.5f;
        int iy = (int)floorf(fy + 0.5f);
        int ix = (int)floorf(fx + 0.5f);
        bool v = (iy >= 0) && (iy < 64) && (ix >= 0) && (ix < 64);
        int iyc = min(max(iy, 0), 63);
        int ixc = min(max(ix, 0), 63);
        g_ilr[m] = v ? (iyc * 64 + ixc) : -1;
        const float rh = 1.0f / 64.0f;
        float qy = v ? (-1.0f + rh + 2.0f * rh * (float)iyc) : 0.0f;
        float qx = v ? (-1.0f + rh + 2.0f * rh * (float)ixc) : 0.0f;
        g_rely[m] = (cy0 - qy) * 64.0f;
        g_relx[m] = (cx0 - qx) * 64.0f;
    }
}

// ---------------- weight prep ----------------
// layers 2..4: W[k][n] fp32 -> [n][Kpad] bf16 hi/lo
__global__ void prep_w_kernel(const float* __restrict__ W, int layer) {
    __nv_bfloat16 *Wh, *Wl;
    int Kpad, N;
    switch (layer) {
        case 2: Wh = g_W2h; Wl = g_W2l; Kpad = KP2; N = NO2; break;
        case 3: Wh = g_W3h; Wl = g_W3l; Kpad = KP3; N = NO3; break;
        default:Wh = g_W4h; Wl = g_W4l; Kpad = KP4; N = NO4; break;
    }
    size_t idx = (size_t)blockIdx.x * blockDim.x + threadIdx.x;
    if (idx >= (size_t)N * Kpad) return;
    int n = (int)(idx / Kpad);
    int k = (int)(idx % Kpad);
    float v = W[(size_t)k * N + n];
    __nv_bfloat16 h, l;
    bf16_split(v, h, l);
    Wh[idx] = h;
    Wl[idx] = l;
}

// WHR[n][k] = w1[128+k][n] + w1[256+k][n]   (k < 128)
__global__ void prep_whr_kernel(const float* __restrict__ w1) {
    size_t idx = (size_t)blockIdx.x * blockDim.x + threadIdx.x;
    if (idx >= (size_t)NO1 * KH) return;
    int n = (int)(idx / KH);
    int k = (int)(idx % KH);
    float v = w1[(size_t)(128 + k) * NO1 + n] + w1[(size_t)(256 + k) * NO1 + n];
    __nv_bfloat16 h, l;
    bf16_split(v, h, l);
    g_WHRh[idx] = h;
    g_WHRl[idx] = l;
}

// WC[n][k] = (k<128) ? w1[k][n] : -w1[128+k][n]   (matches CELL = [feat | lr])
__global__ void prep_wcell_kernel(const float* __restrict__ w1) {
    size_t idx = (size_t)blockIdx.x * blockDim.x + threadIdx.x;
    if (idx >= (size_t)NO1 * KC) return;
    int n = (int)(idx / KC);
    int k = (int)(idx % KC);
    float v = (k < 128) ? w1[(size_t)k * NO1 + n]
                        : -w1[(size_t)(128 + k) * NO1 + n];
    __nv_bfloat16 h, l;
    bf16_split(v, h, l);
    g_WCh[idx] = h;
    g_WCl[idx] = l;
}

// ---------------- one-time fills ----------------
// QHR [m][128] hi/lo: gather hr_guide at ihr (offset-independent), SMEM transpose.
__global__ __launch_bounds__(256) void fill_qhr_kernel(const float* __restrict__ hr) {
    __shared__ float vals[KH][33];
    __shared__ int s_ih[32];
    int t = threadIdx.x;
    int m0 = blockIdx.x * 32;
    if (t < 32) s_ih[t] = g_ihr[m0 + t];
    __syncthreads();
    int ml = t & 31;
    int cb = t >> 5;            // 0..7
    int b = (m0 + ml) >> 16;
    int ih = s_ih[ml];
#pragma unroll 4
    for (int cc = 0; cc < KH; cc += 8) {
        int c = cc + cb;
        vals[c][ml] = (ih >= 0) ? hr[(size_t)(b * 128 + c) * 65536 + ih] : 0.0f;
    }
    __syncthreads();
    int mw = t >> 3;            // 0..31
    int kb = (t & 7) * 16;
    size_t base = (size_t)(m0 + mw) * KH;
#pragma unroll
    for (int kk = 0; kk < 16; kk += 2) {
        int k = kb + kk;
        __nv_bfloat16 h0, l0, h1, l1;
        bf16_split(vals[k][mw], h0, l0);
        bf16_split(vals[k + 1][mw], h1, l1);
        *(__nv_bfloat162*)(g_QHRh + base + k) = __nv_bfloat162(h0, h1);
        *(__nv_bfloat162*)(g_QHRl + base + k) = __nv_bfloat162(l0, l1);
    }
}

// CELL [cellrow][256] hi/lo: cellrow = b*4096 + cell; [feat 128 | lr 128]
__global__ void fill_cell_kernel(const float* __restrict__ feat,
                                 const float* __restrict__ lr) {
    size_t idx = (size_t)blockIdx.x * blockDim.x + threadIdx.x;
    if (idx >= (size_t)NCELL * KC) return;
    int k  = (int)(idx >> 13);          // / 8192
    int cr = (int)(idx & 8191);
    int b = cr >> 12;
    int cell = cr & 4095;
    float v = (k < 128) ? feat[(size_t)(b * 128 + k) * 4096 + cell]
                        : lr[(size_t)(b * 128 + (k - 128)) * 4096 + cell];
    __nv_bfloat16 h, l;
    bf16_split(v, h, l);
    g_CELLh[(size_t)cr * KC + k] = h;
    g_CELLl[(size_t)cr * KC + k] = l;
}

// ---------------- mma.sync GEMM ----------------
// out[m][n] = sum_k A[m][k]*W[n][k]  (+bias, relu, bf16-split  when fuse=1; raw fp32 when fuse=0)
// CTA 128m x 128n, 8 warps (2m x 4n), warp 64m x 32n. K chunks of 64, SW128, double buffer.
#define TILE_BYTES 16384
#define STAGE_BYTES (4 * TILE_BYTES)
#define GEMM_SMEM   (2 * STAGE_BYTES + 1024)

__global__ __launch_bounds__(256) void gemm_mma(int layer, const float* __restrict__ bias) {
    const __nv_bfloat16 *Ah, *Al, *Wh, *Wl;
    __nv_bfloat16 *Oh = nullptr, *Ol = nullptr;
    float* Of = nullptr;
    int Kpad, Nout, fuse;
    switch (layer) {
        case 0: Ah = g_QHRh;  Al = g_QHRl;  Wh = g_WHRh; Wl = g_WHRl; Of = g_YHR; Kpad = KH;  Nout = NO1; fuse = 0; break;
        case 1: Ah = g_CELLh; Al = g_CELLl; Wh = g_WCh;  Wl = g_WCl;  Of = g_Z;   Kpad = KC;  Nout = NO1; fuse = 0; break;
        case 2: Ah = g_X1h;   Al = g_X1l;   Wh = g_W2h;  Wl = g_W2l;  Oh = g_X2h; Ol = g_X2l; Kpad = KP2; Nout = NO2; fuse = 1; break;
        case 3: Ah = g_X2h;   Al = g_X2l;   Wh = g_W3h;  Wl = g_W3l;  Oh = g_X3h; Ol = g_X3l; Kpad = KP3; Nout = NO3; fuse = 1; break;
        default:Ah = g_X3h;   Al = g_X3l;   Wh = g_W4h;  Wl = g_W4l;  Oh = g_X4h; Ol = g_X4l; Kpad = KP4; Nout = NO4; fuse = 1; break;
    }

    extern __shared__ char dsm[];
    __shared__ float s_bias[128];

    int tid = threadIdx.x;
    int wid = tid >> 5;
    int lane = tid & 31;
    int warp_m = wid >> 2;
    int warp_n = wid & 3;
    int n0 = blockIdx.x * 128;
    int m0 = blockIdx.y * 128;

    uint32_t dyn = (smem_u32(dsm) + 1023u) & ~1023u;
    if (fuse && tid < 128) s_bias[tid] = bias[n0 + tid];

    const int NC = Kpad >> 6;

    float acc[4][4][4];
#pragma unroll
    for (int i = 0; i < 4; i++)
#pragma unroll
        for (int j = 0; j < 4; j++)
#pragma unroll
            for (int r = 0; r < 4; r++) acc[i][j][r] = 0.0f;

    uint32_t a_off[4], a_xor[4];
#pragma unroll
    for (int i = 0; i < 4; i++) {
        uint32_t row = warp_m * 64 + i * 16 + (lane & 15);
        a_off[i] = row << 7;
        a_xor[i] = (row & 7) << 4;
    }
    uint32_t w_off[2], w_xor[2];
#pragma unroll
    for (int j2 = 0; j2 < 2; j2++) {
        uint32_t row = warp_n * 32 + j2 * 16 + ((lane >> 4) << 3) + (lane & 7);
        w_off[j2] = row << 7;
        w_xor[j2] = (row & 7) << 4;
    }
    uint32_t a_hi16 = (lane >> 4) << 4;
    uint32_t w_hi16 = ((lane >> 3) & 1) << 4;

    auto issue_loads = [&](int c) {
        uint32_t sb = dyn + (c & 1) * STAGE_BYTES;
        int k0 = c << 6;
#pragma unroll
        for (int it = 0; it < 16; it++) {
            int tile = it >> 2;
            int c2 = ((it & 3) << 8) + tid;
            int row = c2 >> 3;
            int col = c2 & 7;
            const __nv_bfloat16* src;
            size_t gidx;
            if (tile < 2) {
                src = (tile == 0) ? Ah : Al;
                gidx = (size_t)(m0 + row) * Kpad + k0 + col * 8;
            } else {
                src = (tile == 2) ? Wh : Wl;
                gidx = (size_t)(n0 + row) * Kpad + k0 + col * 8;
            }
            uint32_t sa = sb + tile * TILE_BYTES + swz128((row << 7) + (col << 4));
            CP_ASYNC16(sa, __cvta_generic_to_global(src + gidx));
        }
        asm volatile("cp.async.commit_group;" ::: "memory");
    };

    issue_loads(0);

    for (int c = 0; c < NC; c++) {
        if (c + 1 < NC) {
            issue_loads(c + 1);
            asm volatile("cp.async.wait_group 1;" ::: "memory");
        } else {
            asm volatile("cp.async.wait_group 0;" ::: "memory");
        }
        __syncthreads();

        uint32_t sb  = dyn + (c & 1) * STAGE_BYTES;
        uint32_t bAh = sb;
        uint32_t bAl = sb + TILE_BYTES;
        uint32_t bWh = sb + 2 * TILE_BYTES;
        uint32_t bWl = sb + 3 * TILE_BYTES;

#pragma unroll
        for (int ks = 0; ks < 4; ks++) {
            uint32_t bcA = (uint32_t)(ks * 32) + a_hi16;
            uint32_t bcW = (uint32_t)(ks * 32) + w_hi16;
            uint32_t ahi[4][4], alo[4][4];
#pragma unroll
            for (int i = 0; i < 4; i++) {
                uint32_t o = a_off[i] + (bcA ^ a_xor[i]);
                LDSM4(ahi[i], bAh + o);
                LDSM4(alo[i], bAl + o);
            }
            uint32_t bhi[2][4], blo[2][4];
#pragma unroll
            for (int j2 = 0; j2 < 2; j2++) {
                uint32_t o = w_off[j2] + (bcW ^ w_xor[j2]);
                LDSM4(bhi[j2], bWh + o);
                LDSM4(blo[j2], bWl + o);
            }
#pragma unroll
            for (int i = 0; i < 4; i++) {
#pragma unroll
                for (int j = 0; j < 4; j++) {
                    int j2 = j >> 1, jh = (j & 1) << 1;
                    MMA_BF16(acc[i][j], ahi[i], bhi[j2][jh], bhi[j2][jh + 1]);
                    MMA_BF16(acc[i][j], ahi[i], blo[j2][jh], blo[j2][jh + 1]);
                    MMA_BF16(acc[i][j], alo[i], bhi[j2][jh], bhi[j2][jh + 1]);
                }
            }
        }
        __syncthreads();
    }

    int q = lane >> 2, p = lane & 3;
#pragma unroll
    for (int i = 0; i < 4; i++) {
        int r0 = m0 + warp_m * 64 + i * 16 + q;
        size_t o0 = (size_t)r0 * Nout + n0;
        size_t o1 = (size_t)(r0 + 8) * Nout + n0;
#pragma unroll
        for (int j = 0; j < 4; j++) {
            int nn = warp_n * 32 + j * 8 + p * 2;
            if (fuse) {
                float bb0 = s_bias[nn], bb1 = s_bias[nn + 1];
                float v00 = fmaxf(acc[i][j][0] + bb0, 0.0f);
                float v01 = fmaxf(acc[i][j][1] + bb1, 0.0f);
                float v10 = fmaxf(acc[i][j][2] + bb0, 0.0f);
                float v11 = fmaxf(acc[i][j][3] + bb1, 0.0f);
                __nv_bfloat16 h00, l00, h01, l01, h10, l10, h11, l11;
                bf16_split(v00, h00, l00);
                bf16_split(v01, h01, l01);
                bf16_split(v10, h10, l10);
                bf16_split(v11, h11, l11);
                *(__nv_bfloat162*)(Oh + o0 + nn) = __nv_bfloat162(h00, h01);
                *(__nv_bfloat162*)(Ol + o0 + nn) = __nv_bfloat162(l00, l01);
                *(__nv_bfloat162*)(Oh + o1 + nn) = __nv_bfloat162(h10, h11);
                *(__nv_bfloat162*)(Ol + o1 + nn) = __nv_bfloat162(l10, l11);
            } else {
                *(float2*)(Of + o0 + nn) = make_float2(acc[i][j][0], acc[i][j][1]);
                *(float2*)(Of + o1 + nn) = make_float2(acc[i][j][2], acc[i][j][3]);
            }
        }
    }
}

// ---------------- per-pass layer-1 assembly ----------------
// X1[m][n] = relu(YHR[m][n] + Z[b*4096+il][n] + rely*wd0[n] + relx*wd1[n] + b1[n])
__global__ __launch_bounds__(256) void assemble1_kernel(const float* __restrict__ w1,
                                                        const float* __restrict__ b1) {
    __shared__ float s_wd0[NO1], s_wd1[NO1], s_b1[NO1];
    __shared__ int   s_il[16];
    __shared__ float s_ry[16], s_rx[16];
    int t = threadIdx.x;
    int m0 = blockIdx.x * 16;
#pragma unroll
    for (int i = t; i < NO1; i += 256) {
        s_wd0[i] = w1[(size_t)384 * NO1 + i];
        s_wd1[i] = w1[(size_t)385 * NO1 + i];
        s_b1[i]  = b1[i];
    }
    if (t < 16) {
        int m = m0 + t;
        s_il[t] = g_ilr[m];
        s_ry[t] = g_rely[m];
        s_rx[t] = g_relx[m];
    }
    __syncthreads();

    for (int mi = 0; mi < 16; mi++) {
        int m = m0 + mi;
        int b = m >> 16;
        int il = s_il[mi];
        float ry = s_ry[mi], rxx = s_rx[mi];
        const float* zrow = (il >= 0) ? (g_Z + ((size_t)(b * 4096 + il) << 10)) : nullptr;
        size_t ybase = (size_t)m << 10;
#pragma unroll
        for (int it = 0; it < 2; it++) {
            int n = it * 512 + t * 2;
            float2 y = *(const float2*)(g_YHR + ybase + n);
            float z0 = 0.0f, z1 = 0.0f;
            if (zrow) {
                float2 z = *(const float2*)(zrow + n);
                z0 = z.x; z1 = z.y;
            }
            float v0 = fmaxf(y.x + z0 + ry * s_wd0[n]     + rxx * s_wd1[n]     + s_b1[n],     0.0f);
            float v1 = fmaxf(y.y + z1 + ry * s_wd0[n + 1] + rxx * s_wd1[n + 1] + s_b1[n + 1], 0.0f);
            __nv_bfloat16 h0, l0, h1, l1;
            bf16_split(v0, h0, l0);
            bf16_split(v1, h1, l1);
            *(__nv_bfloat162*)(g_X1h + ybase + n) = __nv_bfloat162(h0, h1);
            *(__nv_bfloat162*)(g_X1l + ybase + n) = __nv_bfloat162(l0, l1);
        }
    }
}

// ---------------- layer 5 ----------------
__global__ __launch_bounds__(256) void layer5_kernel(const float* __restrict__ w5,
                                                     const float* __restrict__ b5, int o) {
    __shared__ float ws0[128], ws1[128];
    int t = threadIdx.x;
    if (t < 128) {
        ws0[t] = w5[t * 2 + 0];
        ws1[t] = w5[t * 2 + 1];
    }
    __syncthreads();
    int m = blockIdx.x * 8 + (t >> 5);
    int lane = t & 31;
    size_t base = (size_t)m * 128 + lane * 4;
    __nv_bfloat162 h01 = *(const __nv_bfloat162*)(g_X4h + base);
    __nv_bfloat162 h23 = *(const __nv_bfloat162*)(g_X4h + base + 2);
    __nv_bfloat162 l01 = *(const __nv_bfloat162*)(g_X4l + base);
    __nv_bfloat162 l23 = *(const __nv_bfloat162*)(g_X4l + base + 2);
    float x0 = __bfloat162float(h01.x) + __bfloat162float(l01.x);
    float x1 = __bfloat162float(h01.y) + __bfloat162float(l01.y);
    float x2 = __bfloat162float(h23.x) + __bfloat162float(l23.x);
    float x3 = __bfloat162float(h23.y) + __bfloat162float(l23.y);
    int k = lane * 4;
    float a0 = x0 * ws0[k] + x1 * ws0[k + 1] + x2 * ws0[k + 2] + x3 * ws0[k + 3];
    float a1 = x0 * ws1[k] + x1 * ws1[k + 1] + x2 * ws1[k + 2] + x3 * ws1[k + 3];
#pragma unroll
    for (int s = 16; s > 0; s >>= 1) {
        a0 += __shfl_xor_sync(0xFFFFFFFF, a0, s);
        a1 += __shfl_xor_sync(0xFFFFFFFF, a1, s);
    }
    if (lane == 0) {
        g_P0[o * MTOT + m] = a0 + b5[0];
        g_P1[o * MTOT + m] = a1 + b5[1];
    }
}

// ---------------- softmax combine ----------------
__global__ void combine_kernel(float* __restrict__ out) {
    int m = blockIdx.x * blockDim.x + threadIdx.x;
    if (m >= MTOT) return;
    float l0 = g_P1[0 * MTOT + m];
    float l1 = g_P1[1 * MTOT + m];
    float l2 = g_P1[2 * MTOT + m];
    float l3 = g_P1[3 * MTOT + m];
    float mx = fmaxf(fmaxf(l0, l1), fmaxf(l2, l3));
    float e0 = expf(l0 - mx), e1 = expf(l1 - mx), e2 = expf(l2 - mx), e3 = expf(l3 - mx);
    float s = e0 + e1 + e2 + e3;
    float r = (g_P0[0 * MTOT + m] * e0 + g_P0[1 * MTOT + m] * e1 +
               g_P0[2 * MTOT + m] * e2 + g_P0[3 * MTOT + m] * e3) / s;
    out[m] = r;
}

extern "C" void kernel_launch(void* const* d_in, const int* in_sizes, int n_in,
                              void* d_out, int out_size) {
    const float* feat  = (const float*)d_in[0];
    const float* coord = (const float*)d_in[1];
    const float* hr    = (const float*)d_in[2];
    const float* lr    = (const float*)d_in[3];
    const float* w1 = (const float*)d_in[4];  const float* b1 = (const float*)d_in[5];
    const float* w2 = (const float*)d_in[6];  const float* b2 = (const float*)d_in[7];
    const float* w3 = (const float*)d_in[8];  const float* b3 = (const float*)d_in[9];
    const float* w4 = (const float*)d_in[10]; const float* b4 = (const float*)d_in[11];
    const float* w5 = (const float*)d_in[12]; const float* b5 = (const float*)d_in[13];
    float* out = (float*)d_out;

    cudaFuncSetAttribute(gemm_mma, cudaFuncAttributeMaxDynamicSharedMemorySize, GEMM_SMEM);

    // weight prep
    prep_whr_kernel<<<(unsigned)(((size_t)NO1 * KH + 255) / 256), 256>>>(w1);
    prep_wcell_kernel<<<(unsigned)(((size_t)NO1 * KC + 255) / 256), 256>>>(w1);
    prep_w_kernel<<<(unsigned)(((size_t)NO2 * KP2 + 255) / 256), 256>>>(w2, 2);
    prep_w_kernel<<<(unsigned)(((size_t)NO3 * KP3 + 255) / 256), 256>>>(w3, 3);
    prep_w_kernel<<<(unsigned)(((size_t)NO4 * KP4 + 255) / 256), 256>>>(w4, 4);

    const float offs[4][2] = {{-1.f, -1.f}, {-1.f, 1.f}, {1.f, -1.f}, {1.f, 1.f}};

    // offset-independent precompute: ihr (via meta with offs[0]), QHR, CELL, YHR, Z
    meta_kernel<<<MTOT / 256, 256>>>(coord, offs[0][0], offs[0][1]);
    fill_qhr_kernel<<<MTOT / 32, 256>>>(hr);
    fill_cell_kernel<<<(unsigned)(((size_t)NCELL * KC + 255) / 256), 256>>>(feat, lr);
    gemm_mma<<<dim3(NO1 / 128, MTOT / 128), 256, GEMM_SMEM>>>(0, nullptr);   // YHR
    gemm_mma<<<dim3(NO1 / 128, NCELL / 128), 256, GEMM_SMEM>>>(1, nullptr);  // Z

    for (int o = 0; o < 4; o++) {
        if (o > 0) meta_kernel<<<MTOT / 256, 256>>>(coord, offs[o][0], offs[o][1]);
        assemble1_kernel<<<MTOT / 16, 256>>>(w1, b1);
        gemm_mma<<<dim3(NO2 / 128, MTOT / 128), 256, GEMM_SMEM>>>(2, b2);
        gemm_mma<<<dim3(NO3 / 128, MTOT / 128), 256, GEMM_SMEM>>>(3, b3);
        gemm_mma<<<dim3(NO4 / 128, MTOT / 128), 256, GEMM_SMEM>>>(4, b4);
        layer5_kernel<<<MTOT / 8, 256>>>(w5, b5, o);
    }
    combine_kernel<<<MTOT / 256, 256>>>(out);
}

// round 12
// speedup vs baseline: 4.8991x; 1.0797x over previous
#include <cuda_runtime.h>
#include <cuda_bf16.h>
#include <math.h>
#include <stdint.h>

// JIIF: feat [2,128,64,64], coord [2,65536,2], hr_guide [2,128,256,256], lr_guide [2,128,64,64]
// MLP 386->1024->512->256->128->2, 4 offset passes, M = 131072 (MT4 = 524288 merged rows).
//
// Engine: mma.sync bf16x3-split GEMMs (D = Ahi*Whi + Ahi*Wlo + Alo*Whi), fp32 reg accum,
// 3-stage cp.async pipeline (one barrier per K-chunk), term-reordered independent MMAs.
// Layer-1 decomposition:
//   inp@W1 = q_hr@(W_b+W_c)  [YHR: offset-independent, once]
//          + (q_feat@W_a - q_lr@W_c) [Z: 8192 LR-cell rows, L2-resident]
//          + rel@W_d                  [fused FMAs in assemble]
// All 4 offsets merged into one M=524288 batch for layers 2-4 + layer 5.
//
// MEMORY: single 3GB arena with lifetime-based aliasing (aarch64 .bss must stay < 4GB):
//   Region A [0,2GB):   X1h|X1l;  after layer-2: X3h|X3l|X4h|X4l alias here.
//   Region B [2GB,3GB): X2h|X2l;  before layer-2: YHR aliases X2h; QHR+CELL alias X2l.

#define MTOT 131072
#define MT4  (4 * MTOT)
#define NCELL 8192

#define KH  128
#define KC  256
#define KP2 1024
#define KP3 512
#define KP4 256
#define NO1 1024
#define NO2 512
#define NO3 256
#define NO4 128

// ---------------- arena ----------------
#define SZ_X1H  ((size_t)MT4 * NO1 * 2)        // 1 GB
#define SZ_X2H  ((size_t)MT4 * NO2 * 2)        // 512 MB
#define SZ_X3H  ((size_t)MT4 * NO3 * 2)        // 256 MB
#define SZ_X4H  ((size_t)MT4 * NO4 * 2)        // 128 MB
#define SZ_QHRH ((size_t)MTOT * KH * 2)        // 32 MB
#define SZ_CELLH ((size_t)NCELL * KC * 2)      // 4 MB

#define A_X1H   ((size_t)0)
#define A_X1L   (A_X1H + SZ_X1H)
#define A_X2H   (A_X1L + SZ_X1H)               // 2 GB
#define A_X2L   (A_X2H + SZ_X2H)               // 2.5 GB
#define ARENA_SZ (A_X2L + SZ_X2H)              // 3 GB
// aliases, region A (live only after layer-2 consumed X1):
#define A_X3H   A_X1H
#define A_X3L   (A_X3H + SZ_X3H)
#define A_X4H   (A_X3L + SZ_X3H)
#define A_X4L   (A_X4H + SZ_X4H)
// aliases, region B (dead before layer-2 writes X2):
#define A_YHR   A_X2H                          // fp32 MTOT*NO1*4 = 512 MB = SZ_X2H exactly
#define A_QHRH  A_X2L
#define A_QHRL  (A_QHRH + SZ_QHRH)
#define A_CELLH (A_QHRL + SZ_QHRH)
#define A_CELLL (A_CELLH + SZ_CELLH)

__device__ __align__(1024) char g_arena[ARENA_SZ];

#define P_X1h   ((__nv_bfloat16*)(g_arena + A_X1H))
#define P_X1l   ((__nv_bfloat16*)(g_arena + A_X1L))
#define P_X2h   ((__nv_bfloat16*)(g_arena + A_X2H))
#define P_X2l   ((__nv_bfloat16*)(g_arena + A_X2L))
#define P_X3h   ((__nv_bfloat16*)(g_arena + A_X3H))
#define P_X3l   ((__nv_bfloat16*)(g_arena + A_X3L))
#define P_X4h   ((__nv_bfloat16*)(g_arena + A_X4H))
#define P_X4l   ((__nv_bfloat16*)(g_arena + A_X4L))
#define P_YHR   ((float*)(g_arena + A_YHR))
#define P_QHRh  ((__nv_bfloat16*)(g_arena + A_QHRH))
#define P_QHRl  ((__nv_bfloat16*)(g_arena + A_QHRL))
#define P_CELLh ((__nv_bfloat16*)(g_arena + A_CELLH))
#define P_CELLl ((__nv_bfloat16*)(g_arena + A_CELLL))

// ---------------- small globals ----------------
__device__ float g_Z[(size_t)NCELL * NO1];

__device__ __nv_bfloat16 g_WHRh[(size_t)NO1 * KH];
__device__ __nv_bfloat16 g_WHRl[(size_t)NO1 * KH];
__device__ __nv_bfloat16 g_WCh[(size_t)NO1 * KC];
__device__ __nv_bfloat16 g_WCl[(size_t)NO1 * KC];
__device__ __nv_bfloat16 g_W2h[(size_t)NO2 * KP2];
__device__ __nv_bfloat16 g_W2l[(size_t)NO2 * KP2];
__device__ __nv_bfloat16 g_W3h[(size_t)NO3 * KP3];
__device__ __nv_bfloat16 g_W3l[(size_t)NO3 * KP3];
__device__ __nv_bfloat16 g_W4h[(size_t)NO4 * KP4];
__device__ __nv_bfloat16 g_W4l[(size_t)NO4 * KP4];

__device__ float g_P0[MT4];
__device__ float g_P1[MT4];
__device__ int   g_ihr[MTOT];
__device__ int   g_ilr4[MT4];
__device__ float g_rely4[MT4];
__device__ float g_relx4[MT4];

// ---------------- helpers ----------------
__device__ __forceinline__ uint32_t smem_u32(const void* p) {
    uint32_t a;
    asm("{ .reg .u64 t; cvta.to.shared.u64 t, %1; cvt.u32.u64 %0, t; }" : "=r"(a) : "l"(p));
    return a;
}
__device__ __forceinline__ uint32_t swz128(uint32_t off) {
    return off ^ ((off >> 3) & 0x70);
}
__device__ __forceinline__ void bf16_split(float v, __nv_bfloat16& h, __nv_bfloat16& l) {
    h = __float2bfloat16(v);
    l = __float2bfloat16(v - __bfloat162float(h));
}

#define LDSM4(r, addr) \
    asm volatile("ldmatrix.sync.aligned.m8n8.x4.shared.b16 {%0,%1,%2,%3}, [%4];" \
        : "=r"((r)[0]), "=r"((r)[1]), "=r"((r)[2]), "=r"((r)[3]) : "r"(addr))

#define MMA_BF16(dd, aa, b0, b1) \
    asm volatile("mma.sync.aligned.m16n8k16.row.col.f32.bf16.bf16.f32 " \
        "{%0,%1,%2,%3}, {%4,%5,%6,%7}, {%8,%9}, {%0,%1,%2,%3};" \
        : "+f"((dd)[0]), "+f"((dd)[1]), "+f"((dd)[2]), "+f"((dd)[3]) \
        : "r"((aa)[0]), "r"((aa)[1]), "r"((aa)[2]), "r"((aa)[3]), "r"(b0), "r"(b1))

#define CP_ASYNC16(sa, ga) \
    asm volatile("cp.async.cg.shared.global [%0], [%1], 16;" :: "r"(sa), "l"(ga) : "memory")

// ---------------- meta (all 4 offsets) ----------------
__global__ void meta_kernel(const float* __restrict__ coord) {
    int m = blockIdx.x * blockDim.x + threadIdx.x;
    if (m >= MTOT) return;
    float cy0 = coord[2 * m + 0];
    float cx0 = coord[2 * m + 1];
    {
        float fy = (cy0 + 1.0f) * 128.0f - 0.5f;
        float fx = (cx0 + 1.0f) * 128.0f - 0.5f;
        int iy = (int)floorf(fy + 0.5f);
        int ix = (int)floorf(fx + 0.5f);
        bool v = (iy >= 0) && (iy < 256) && (ix >= 0) && (ix < 256);
        int iyc = min(max(iy, 0), 255);
        int ixc = min(max(ix, 0), 255);
        g_ihr[m] = v ? (iyc * 256 + ixc) : -1;
    }
#pragma unroll
    for (int o = 0; o < 4; o++) {
        float vx = (o < 2) ? -1.0f : 1.0f;      // row offset (cy)
        float vy = (o & 1) ? 1.0f : -1.0f;      // col offset (cx)
        float cy = cy0 + vx * (1.0f / 64.0f);
        float cx = cx0 + vy * (1.0f / 64.0f);
        float fy = (cy + 1.0f) * 32.0f - 0.5f;
        float fx = (cx + 1.0f) * 32.0f - 0.5f;
        int iy = (int)floorf(fy + 0.5f);
        int ix = (int)floorf(fx + 0.5f);
        bool v = (iy >= 0) && (iy < 64) && (ix >= 0) && (ix < 64);
        int iyc = min(max(iy, 0), 63);
        int ixc = min(max(ix, 0), 63);
        g_ilr4[o * MTOT + m] = v ? (iyc * 64 + ixc) : -1;
        const float rh = 1.0f / 64.0f;
        float qy = v ? (-1.0f + rh + 2.0f * rh * (float)iyc) : 0.0f;
        float qx = v ? (-1.0f + rh + 2.0f * rh * (float)ixc) : 0.0f;
        g_rely4[o * MTOT + m] = (cy0 - qy) * 64.0f;
        g_relx4[o * MTOT + m] = (cx0 - qx) * 64.0f;
    }
}

// ---------------- weight prep ----------------
__global__ void prep_w_kernel(const float* __restrict__ W, int layer) {
    __nv_bfloat16 *Wh, *Wl;
    int Kpad, N;
    switch (layer) {
        case 2: Wh = g_W2h; Wl = g_W2l; Kpad = KP2; N = NO2; break;
        case 3: Wh = g_W3h; Wl = g_W3l; Kpad = KP3; N = NO3; break;
        default:Wh = g_W4h; Wl = g_W4l; Kpad = KP4; N = NO4; break;
    }
    size_t idx = (size_t)blockIdx.x * blockDim.x + threadIdx.x;
    if (idx >= (size_t)N * Kpad) return;
    int n = (int)(idx / Kpad);
    int k = (int)(idx % Kpad);
    float v = W[(size_t)k * N + n];
    __nv_bfloat16 h, l;
    bf16_split(v, h, l);
    Wh[idx] = h;
    Wl[idx] = l;
}

__global__ void prep_whr_kernel(const float* __restrict__ w1) {
    size_t idx = (size_t)blockIdx.x * blockDim.x + threadIdx.x;
    if (idx >= (size_t)NO1 * KH) return;
    int n = (int)(idx / KH);
    int k = (int)(idx % KH);
    float v = w1[(size_t)(128 + k) * NO1 + n] + w1[(size_t)(256 + k) * NO1 + n];
    __nv_bfloat16 h, l;
    bf16_split(v, h, l);
    g_WHRh[idx] = h;
    g_WHRl[idx] = l;
}

__global__ void prep_wcell_kernel(const float* __restrict__ w1) {
    size_t idx = (size_t)blockIdx.x * blockDim.x + threadIdx.x;
    if (idx >= (size_t)NO1 * KC) return;
    int n = (int)(idx / KC);
    int k = (int)(idx % KC);
    float v = (k < 128) ? w1[(size_t)k * NO1 + n]
                        : -w1[(size_t)(128 + k) * NO1 + n];
    __nv_bfloat16 h, l;
    bf16_split(v, h, l);
    g_WCh[idx] = h;
    g_WCl[idx] = l;
}

// ---------------- one-time fills ----------------
__global__ __launch_bounds__(256) void fill_qhr_kernel(const float* __restrict__ hr) {
    __shared__ float vals[KH][33];
    __shared__ int s_ih[32];
    int t = threadIdx.x;
    int m0 = blockIdx.x * 32;
    if (t < 32) s_ih[t] = g_ihr[m0 + t];
    __syncthreads();
    int ml = t & 31;
    int cb = t >> 5;
    int b = (m0 + ml) >> 16;
    int ih = s_ih[ml];
#pragma unroll 4
    for (int cc = 0; cc < KH; cc += 8) {
        int c = cc + cb;
        vals[c][ml] = (ih >= 0) ? hr[(size_t)(b * 128 + c) * 65536 + ih] : 0.0f;
    }
    __syncthreads();
    int mw = t >> 3;
    int kb = (t & 7) * 16;
    size_t base = (size_t)(m0 + mw) * KH;
#pragma unroll
    for (int kk = 0; kk < 16; kk += 2) {
        int k = kb + kk;
        __nv_bfloat16 h0, l0, h1, l1;
        bf16_split(vals[k][mw], h0, l0);
        bf16_split(vals[k + 1][mw], h1, l1);
        *(__nv_bfloat162*)(P_QHRh + base + k) = __nv_bfloat162(h0, h1);
        *(__nv_bfloat162*)(P_QHRl + base + k) = __nv_bfloat162(l0, l1);
    }
}

__global__ void fill_cell_kernel(const float* __restrict__ feat,
                                 const float* __restrict__ lr) {
    size_t idx = (size_t)blockIdx.x * blockDim.x + threadIdx.x;
    if (idx >= (size_t)NCELL * KC) return;
    int k  = (int)(idx >> 13);
    int cr = (int)(idx & 8191);
    int b = cr >> 12;
    int cell = cr & 4095;
    float v = (k < 128) ? feat[(size_t)(b * 128 + k) * 4096 + cell]
                        : lr[(size_t)(b * 128 + (k - 128)) * 4096 + cell];
    __nv_bfloat16 h, l;
    bf16_split(v, h, l);
    P_CELLh[(size_t)cr * KC + k] = h;
    P_CELLl[(size_t)cr * KC + k] = l;
}

// ---------------- mma.sync GEMM (3-stage pipeline, term-reordered) ----------------
#define TILE_BYTES 16384
#define STAGE_BYTES (4 * TILE_BYTES)
#define NSTAGE 3
#define GEMM_SMEM   (NSTAGE * STAGE_BYTES + 1024)

__global__ __launch_bounds__(256) void gemm_mma(int layer, const float* __restrict__ bias) {
    const __nv_bfloat16 *Ah, *Al, *Wh, *Wl;
    __nv_bfloat16 *Oh = nullptr, *Ol = nullptr;
    float* Of = nullptr;
    int Kpad, Nout, fuse;
    switch (layer) {
        case 0: Ah = P_QHRh;  Al = P_QHRl;  Wh = g_WHRh; Wl = g_WHRl; Of = P_YHR; Kpad = KH;  Nout = NO1; fuse = 0; break;
        case 1: Ah = P_CELLh; Al = P_CELLl; Wh = g_WCh;  Wl = g_WCl;  Of = g_Z;   Kpad = KC;  Nout = NO1; fuse = 0; break;
        case 2: Ah = P_X1h;   Al = P_X1l;   Wh = g_W2h;  Wl = g_W2l;  Oh = P_X2h; Ol = P_X2l; Kpad = KP2; Nout = NO2; fuse = 1; break;
        case 3: Ah = P_X2h;   Al = P_X2l;   Wh = g_W3h;  Wl = g_W3l;  Oh = P_X3h; Ol = P_X3l; Kpad = KP3; Nout = NO3; fuse = 1; break;
        default:Ah = P_X3h;   Al = P_X3l;   Wh = g_W4h;  Wl = g_W4l;  Oh = P_X4h; Ol = P_X4l; Kpad = KP4; Nout = NO4; fuse = 1; break;
    }

    extern __shared__ char dsm[];
    __shared__ float s_bias[128];

    int tid = threadIdx.x;
    int wid = tid >> 5;
    int lane = tid & 31;
    int warp_m = wid >> 2;
    int warp_n = wid & 3;
    int n0 = blockIdx.x * 128;
    int m0 = blockIdx.y * 128;

    uint32_t dyn = (smem_u32(dsm) + 1023u) & ~1023u;
    if (fuse && tid < 128) s_bias[tid] = bias[n0 + tid];

    const int NC = Kpad >> 6;

    float acc[4][4][4];
#pragma unroll
    for (int i = 0; i < 4; i++)
#pragma unroll
        for (int j = 0; j < 4; j++)
#pragma unroll
            for (int r = 0; r < 4; r++) acc[i][j][r] = 0.0f;

    uint32_t a_off[4], a_xor[4];
#pragma unroll
    for (int i = 0; i < 4; i++) {
        uint32_t row = warp_m * 64 + i * 16 + (lane & 15);
        a_off[i] = row << 7;
        a_xor[i] = (row & 7) << 4;
    }
    uint32_t w_off[2], w_xor[2];
#pragma unroll
    for (int j2 = 0; j2 < 2; j2++) {
        uint32_t row = warp_n * 32 + j2 * 16 + ((lane >> 4) << 3) + (lane & 7);
        w_off[j2] = row << 7;
        w_xor[j2] = (row & 7) << 4;
    }
    uint32_t a_hi16 = (lane >> 4) << 4;
    uint32_t w_hi16 = ((lane >> 3) & 1) << 4;

    auto issue_loads = [&](int c) {
        uint32_t sb = dyn + (c % NSTAGE) * STAGE_BYTES;
        int k0 = c << 6;
#pragma unroll
        for (int it = 0; it < 16; it++) {
            int tile = it >> 2;
            int c2 = ((it & 3) << 8) + tid;
            int row = c2 >> 3;
            int col = c2 & 7;
            const __nv_bfloat16* src;
            size_t gidx;
            if (tile < 2) {
                src = (tile == 0) ? Ah : Al;
                gidx = (size_t)(m0 + row) * Kpad + k0 + col * 8;
            } else {
                src = (tile == 2) ? Wh : Wl;
                gidx = (size_t)(n0 + row) * Kpad + k0 + col * 8;
            }
            uint32_t sa = sb + tile * TILE_BYTES + swz128((row << 7) + (col << 4));
            CP_ASYNC16(sa, __cvta_generic_to_global(src + gidx));
        }
    };

    issue_loads(0);
    asm volatile("cp.async.commit_group;" ::: "memory");
    if (NC > 1) issue_loads(1);
    asm volatile("cp.async.commit_group;" ::: "memory");

    for (int c = 0; c < NC; c++) {
        asm volatile("cp.async.wait_group %0;" :: "n"(NSTAGE - 2) : "memory");
        __syncthreads();

        if (c + NSTAGE - 1 < NC) issue_loads(c + NSTAGE - 1);
        asm volatile("cp.async.commit_group;" ::: "memory");

        uint32_t sb  = dyn + (c % NSTAGE) * STAGE_BYTES;
        uint32_t bAh = sb;
        uint32_t bAl = sb + TILE_BYTES;
        uint32_t bWh = sb + 2 * TILE_BYTES;
        uint32_t bWl = sb + 3 * TILE_BYTES;

#pragma unroll
        for (int ks = 0; ks < 4; ks++) {
            uint32_t bcA = (uint32_t)(ks * 32) + a_hi16;
            uint32_t bcW = (uint32_t)(ks * 32) + w_hi16;
            uint32_t ahi[4][4], alo[4][4];
#pragma unroll
            for (int i = 0; i < 4; i++) {
                uint32_t o = a_off[i] + (bcA ^ a_xor[i]);
                LDSM4(ahi[i], bAh + o);
                LDSM4(alo[i], bAl + o);
            }
            uint32_t bhi[2][4], blo[2][4];
#pragma unroll
            for (int j2 = 0; j2 < 2; j2++) {
                uint32_t o = w_off[j2] + (bcW ^ w_xor[j2]);
                LDSM4(bhi[j2], bWh + o);
                LDSM4(blo[j2], bWl + o);
            }
            // term-reordered: 16 independent MMAs per term (no RAW chains)
#pragma unroll
            for (int i = 0; i < 4; i++)
#pragma unroll
                for (int j = 0; j < 4; j++) {
                    int j2 = j >> 1, jh = (j & 1) << 1;
                    MMA_BF16(acc[i][j], ahi[i], bhi[j2][jh], bhi[j2][jh + 1]);
                }
#pragma unroll
            for (int i = 0; i < 4; i++)
#pragma unroll
                for (int j = 0; j < 4; j++) {
                    int j2 = j >> 1, jh = (j & 1) << 1;
                    MMA_BF16(acc[i][j], ahi[i], blo[j2][jh], blo[j2][jh + 1]);
                }
#pragma unroll
            for (int i = 0; i < 4; i++)
#pragma unroll
                for (int j = 0; j < 4; j++) {
                    int j2 = j >> 1, jh = (j & 1) << 1;
                    MMA_BF16(acc[i][j], alo[i], bhi[j2][jh], bhi[j2][jh + 1]);
                }
        }
    }

    int q = lane >> 2, p = lane & 3;
#pragma unroll
    for (int i = 0; i < 4; i++) {
        int r0 = m0 + warp_m * 64 + i * 16 + q;
        size_t o0 = (size_t)r0 * Nout + n0;
        size_t o1 = (size_t)(r0 + 8) * Nout + n0;
#pragma unroll
        for (int j = 0; j < 4; j++) {
            int nn = warp_n * 32 + j * 8 + p * 2;
            if (fuse) {
                float bb0 = s_bias[nn], bb1 = s_bias[nn + 1];
                float v00 = fmaxf(acc[i][j][0] + bb0, 0.0f);
                float v01 = fmaxf(acc[i][j][1] + bb1, 0.0f);
                float v10 = fmaxf(acc[i][j][2] + bb0, 0.0f);
                float v11 = fmaxf(acc[i][j][3] + bb1, 0.0f);
                __nv_bfloat16 h00, l00, h01, l01, h10, l10, h11, l11;
                bf16_split(v00, h00, l00);
                bf16_split(v01, h01, l01);
                bf16_split(v10, h10, l10);
                bf16_split(v11, h11, l11);
                *(__nv_bfloat162*)(Oh + o0 + nn) = __nv_bfloat162(h00, h01);
                *(__nv_bfloat162*)(Ol + o0 + nn) = __nv_bfloat162(l00, l01);
                *(__nv_bfloat162*)(Oh + o1 + nn) = __nv_bfloat162(h10, h11);
                *(__nv_bfloat162*)(Ol + o1 + nn) = __nv_bfloat162(l10, l11);
            } else {
                *(float2*)(Of + o0 + nn) = make_float2(acc[i][j][0], acc[i][j][1]);
                *(float2*)(Of + o1 + nn) = make_float2(acc[i][j][2], acc[i][j][3]);
            }
        }
    }
}

// ---------------- fused layer-1 assembly for ALL 4 offsets ----------------
__global__ __launch_bounds__(256) void assemble_all_kernel(const float* __restrict__ w1,
                                                           const float* __restrict__ b1) {
    __shared__ float s_wd0[NO1], s_wd1[NO1], s_b1[NO1];
    __shared__ int   s_il[4][8];
    __shared__ float s_ry[4][8], s_rx[4][8];
    int t = threadIdx.x;
    int m0 = blockIdx.x * 8;
#pragma unroll
    for (int i = t; i < NO1; i += 256) {
        s_wd0[i] = w1[(size_t)384 * NO1 + i];
        s_wd1[i] = w1[(size_t)385 * NO1 + i];
        s_b1[i]  = b1[i];
    }
    if (t < 32) {
        int o = t >> 3, pi = t & 7;
        int m = m0 + pi;
        s_il[o][pi] = g_ilr4[o * MTOT + m];
        s_ry[o][pi] = g_rely4[o * MTOT + m];
        s_rx[o][pi] = g_relx4[o * MTOT + m];
    }
    __syncthreads();

    for (int pi = 0; pi < 8; pi++) {
        int m = m0 + pi;
        int b = m >> 16;
        size_t ybase = (size_t)m << 10;
#pragma unroll
        for (int it = 0; it < 2; it++) {
            int n = it * 512 + t * 2;
            float2 y = *(const float2*)(P_YHR + ybase + n);
            float wd0a = s_wd0[n], wd0b = s_wd0[n + 1];
            float wd1a = s_wd1[n], wd1b = s_wd1[n + 1];
            float ba = s_b1[n], bb = s_b1[n + 1];
#pragma unroll
            for (int o = 0; o < 4; o++) {
                int il = s_il[o][pi];
                float z0 = 0.0f, z1 = 0.0f;
                if (il >= 0) {
                    float2 z = *(const float2*)(g_Z + (((size_t)(b * 4096 + il)) << 10) + n);
                    z0 = z.x; z1 = z.y;
                }
                float ry = s_ry[o][pi], rxx = s_rx[o][pi];
                float v0 = fmaxf(y.x + z0 + ry * wd0a + rxx * wd1a + ba, 0.0f);
                float v1 = fmaxf(y.y + z1 + ry * wd0b + rxx * wd1b + bb, 0.0f);
                __nv_bfloat16 h0, l0, h1, l1;
                bf16_split(v0, h0, l0);
                bf16_split(v1, h1, l1);
                size_t obase = ((size_t)(o * MTOT + m) << 10) + n;
                *(__nv_bfloat162*)(P_X1h + obase) = __nv_bfloat162(h0, h1);
                *(__nv_bfloat162*)(P_X1l + obase) = __nv_bfloat162(l0, l1);
            }
        }
    }
}

// ---------------- layer 5 (merged M = 524288) ----------------
__global__ __launch_bounds__(256) void layer5_kernel(const float* __restrict__ w5,
                                                     const float* __restrict__ b5) {
    __shared__ float ws0[128], ws1[128];
    int t = threadIdx.x;
    if (t < 128) {
        ws0[t] = w5[t * 2 + 0];
        ws1[t] = w5[t * 2 + 1];
    }
    __syncthreads();
    int m = blockIdx.x * 8 + (t >> 5);
    int lane = t & 31;
    size_t base = (size_t)m * 128 + lane * 4;
    __nv_bfloat162 h01 = *(const __nv_bfloat162*)(P_X4h + base);
    __nv_bfloat162 h23 = *(const __nv_bfloat162*)(P_X4h + base + 2);
    __nv_bfloat162 l01 = *(const __nv_bfloat162*)(P_X4l + base);
    __nv_bfloat162 l23 = *(const __nv_bfloat162*)(P_X4l + base + 2);
    float x0 = __bfloat162float(h01.x) + __bfloat162float(l01.x);
    float x1 = __bfloat162float(h01.y) + __bfloat162float(l01.y);
    float x2 = __bfloat162float(h23.x) + __bfloat162float(l23.x);
    float x3 = __bfloat162float(h23.y) + __bfloat162float(l23.y);
    int k = lane * 4;
    float a0 = x0 * ws0[k] + x1 * ws0[k + 1] + x2 * ws0[k + 2] + x3 * ws0[k + 3];
    float a1 = x0 * ws1[k] + x1 * ws1[k + 1] + x2 * ws1[k + 2] + x3 * ws1[k + 3];
#pragma unroll
    for (int s = 16; s > 0; s >>= 1) {
        a0 += __shfl_xor_sync(0xFFFFFFFF, a0, s);
        a1 += __shfl_xor_sync(0xFFFFFFFF, a1, s);
    }
    if (lane == 0) {
        g_P0[m] = a0 + b5[0];
        g_P1[m] = a1 + b5[1];
    }
}

// ---------------- softmax combine ----------------
__global__ void combine_kernel(float* __restrict__ out) {
    int m = blockIdx.x * blockDim.x + threadIdx.x;
    if (m >= MTOT) return;
    float l0 = g_P1[0 * MTOT + m];
    float l1 = g_P1[1 * MTOT + m];
    float l2 = g_P1[2 * MTOT + m];
    float l3 = g_P1[3 * MTOT + m];
    float mx = fmaxf(fmaxf(l0, l1), fmaxf(l2, l3));
    float e0 = expf(l0 - mx), e1 = expf(l1 - mx), e2 = expf(l2 - mx), e3 = expf(l3 - mx);
    float s = e0 + e1 + e2 + e3;
    float r = (g_P0[0 * MTOT + m] * e0 + g_P0[1 * MTOT + m] * e1 +
               g_P0[2 * MTOT + m] * e2 + g_P0[3 * MTOT + m] * e3) / s;
    out[m] = r;
}

extern "C" void kernel_launch(void* const* d_in, const int* in_sizes, int n_in,
                              void* d_out, int out_size) {
    const float* feat  = (const float*)d_in[0];
    const float* coord = (const float*)d_in[1];
    const float* hr    = (const float*)d_in[2];
    const float* lr    = (const float*)d_in[3];
    const float* w1 = (const float*)d_in[4];  const float* b1 = (const float*)d_in[5];
    const float* w2 = (const float*)d_in[6];  const float* b2 = (const float*)d_in[7];
    const float* w3 = (const float*)d_in[8];  const float* b3 = (const float*)d_in[9];
    const float* w4 = (const float*)d_in[10]; const float* b4 = (const float*)d_in[11];
    const float* w5 = (const float*)d_in[12]; const float* b5 = (const float*)d_in[13];
    float* out = (float*)d_out;

    cudaFuncSetAttribute(gemm_mma, cudaFuncAttributeMaxDynamicSharedMemorySize, GEMM_SMEM);

    // weight prep
    prep_whr_kernel<<<(unsigned)(((size_t)NO1 * KH + 255) / 256), 256>>>(w1);
    prep_wcell_kernel<<<(unsigned)(((size_t)NO1 * KC + 255) / 256), 256>>>(w1);
    prep_w_kernel<<<(unsigned)(((size_t)NO2 * KP2 + 255) / 256), 256>>>(w2, 2);
    prep_w_kernel<<<(unsigned)(((size_t)NO3 * KP3 + 255) / 256), 256>>>(w3, 3);
    prep_w_kernel<<<(unsigned)(((size_t)NO4 * KP4 + 255) / 256), 256>>>(w4, 4);

    // offset-independent precompute
    meta_kernel<<<MTOT / 256, 256>>>(coord);
    fill_qhr_kernel<<<MTOT / 32, 256>>>(hr);
    fill_cell_kernel<<<(unsigned)(((size_t)NCELL * KC + 255) / 256), 256>>>(feat, lr);
    gemm_mma<<<dim3(NO1 / 128, MTOT / 128), 256, GEMM_SMEM>>>(0, nullptr);   // YHR
    gemm_mma<<<dim3(NO1 / 128, NCELL / 128), 256, GEMM_SMEM>>>(1, nullptr);  // Z

    // merged 4-offset batch
    assemble_all_kernel<<<MTOT / 8, 256>>>(w1, b1);
    gemm_mma<<<dim3(NO2 / 128, MT4 / 128), 256, GEMM_SMEM>>>(2, b2);
    gemm_mma<<<dim3(NO3 / 128, MT4 / 128), 256, GEMM_SMEM>>>(3, b3);
    gemm_mma<<<dim3(NO4 / 128, MT4 / 128), 256, GEMM_SMEM>>>(4, b4);
    layer5_kernel<<<MT4 / 8, 256>>>(w5, b5);
    combine_kernel<<<MTOT / 256, 256>>>(out);
}

// round 16
// speedup vs baseline: 5.9655x; 1.2177x over previous
#include <cuda_runtime.h>
#include <cuda_fp16.h>
#include <math.h>
#include <stdint.h>

// JIIF: feat [2,128,64,64], coord [2,65536,2], hr_guide [2,128,256,256], lr_guide [2,128,64,64]
// MLP 386->1024->512->256->128->2, 4 offset passes merged: MT4 = 524288 rows.
//
// Engine: mma.sync fp16 GEMMs, fp32 reg accum, 3-stage cp.async pipeline.
//  - Layers 2-4 (95% of MACs): A split fp16 (hi+lo, exact to 2^-24), W single fp16
//    => out = A @ f16(W) exactly; error = fp16 weight quantization (~2.4e-4/layer). 2 MMAs/tile.
//  - Layer-1 GEMMs (YHR, Z): 3-term fp16 split (error 2^-22). 3 MMAs/tile.
// Layer-1 decomposition:
//   inp@W1 = q_hr@(W_b+W_c)  [YHR, offset-independent, once]
//          + (q_feat@W_a - q_lr@W_c) [Z: 8192 LR-cell rows]
//          + rel@W_d                  [fused FMAs in assemble]
// MEMORY: 3GB arena, lifetime-aliased (aarch64 .bss < 4GB).

#define MTOT 131072
#define MT4  (4 * MTOT)
#define NCELL 8192

#define KH  128
#define KC  256
#define KP2 1024
#define KP3 512
#define KP4 256
#define NO1 1024
#define NO2 512
#define NO3 256
#define NO4 128

// ---------------- arena ----------------
#define SZ_X1H  ((size_t)MT4 * NO1 * 2)        // 1 GB
#define SZ_X2H  ((size_t)MT4 * NO2 * 2)        // 512 MB
#define SZ_X3H  ((size_t)MT4 * NO3 * 2)        // 256 MB
#define SZ_X4H  ((size_t)MT4 * NO4 * 2)        // 128 MB
#define SZ_QHRH ((size_t)MTOT * KH * 2)        // 32 MB
#define SZ_CELLH ((size_t)NCELL * KC * 2)      // 4 MB

#define A_X1H   ((size_t)0)
#define A_X1L   (A_X1H + SZ_X1H)
#define A_X2H   (A_X1L + SZ_X1H)               // 2 GB
#define A_X2L   (A_X2H + SZ_X2H)               // 2.5 GB
#define ARENA_SZ (A_X2L + SZ_X2H)              // 3 GB
// aliases, region A (live only after layer-2 consumed X1):
#define A_X3H   A_X1H
#define A_X3L   (A_X3H + SZ_X3H)
#define A_X4H   (A_X3L + SZ_X3H)
#define A_X4L   (A_X4H + SZ_X4H)
// aliases, region B (dead before layer-2 writes X2):
#define A_YHR   A_X2H                          // fp32 MTOT*NO1*4 = 512 MB = SZ_X2H exactly
#define A_QHRH  A_X2L
#define A_QHRL  (A_QHRH + SZ_QHRH)
#define A_CELLH (A_QHRL + SZ_QHRH)
#define A_CELLL (A_CELLH + SZ_CELLH)

__device__ __align__(1024) char g_arena[ARENA_SZ];

#define P_X1h   ((__half*)(g_arena + A_X1H))
#define P_X1l   ((__half*)(g_arena + A_X1L))
#define P_X2h   ((__half*)(g_arena + A_X2H))
#define P_X2l   ((__half*)(g_arena + A_X2L))
#define P_X3h   ((__half*)(g_arena + A_X3H))
#define P_X3l   ((__half*)(g_arena + A_X3L))
#define P_X4h   ((__half*)(g_arena + A_X4H))
#define P_X4l   ((__half*)(g_arena + A_X4L))
#define P_YHR   ((float*)(g_arena + A_YHR))
#define P_QHRh  ((__half*)(g_arena + A_QHRH))
#define P_QHRl  ((__half*)(g_arena + A_QHRL))
#define P_CELLh ((__half*)(g_arena + A_CELLH))
#define P_CELLl ((__half*)(g_arena + A_CELLL))

// ---------------- small globals ----------------
__device__ float g_Z[(size_t)NCELL * NO1];

__device__ __half g_WHRh[(size_t)NO1 * KH];
__device__ __half g_WHRl[(size_t)NO1 * KH];
__device__ __half g_WCh[(size_t)NO1 * KC];
__device__ __half g_WCl[(size_t)NO1 * KC];
__device__ __half g_W2[(size_t)NO2 * KP2];
__device__ __half g_W3[(size_t)NO3 * KP3];
__device__ __half g_W4[(size_t)NO4 * KP4];

__device__ float g_P0[MT4];
__device__ float g_P1[MT4];
__device__ int   g_ihr[MTOT];
__device__ int   g_ilr4[MT4];
__device__ float g_rely4[MT4];
__device__ float g_relx4[MT4];

// ---------------- helpers ----------------
__device__ __forceinline__ uint32_t smem_u32(const void* p) {
    uint32_t a;
    asm("{ .reg .u64 t; cvta.to.shared.u64 t, %1; cvt.u32.u64 %0, t; }" : "=r"(a) : "l"(p));
    return a;
}
__device__ __forceinline__ uint32_t swz128(uint32_t off) {
    return off ^ ((off >> 3) & 0x70);
}
__device__ __forceinline__ void f16_split(float v, __half& h, __half& l) {
    h = __float2half_rn(v);
    l = __float2half_rn(v - __half2float(h));
}

#define LDSM4(r, addr) \
    asm volatile("ldmatrix.sync.aligned.m8n8.x4.shared.b16 {%0,%1,%2,%3}, [%4];" \
        : "=r"((r)[0]), "=r"((r)[1]), "=r"((r)[2]), "=r"((r)[3]) : "r"(addr))

#define MMA_F16(dd, aa, b0, b1) \
    asm volatile("mma.sync.aligned.m16n8k16.row.col.f32.f16.f16.f32 " \
        "{%0,%1,%2,%3}, {%4,%5,%6,%7}, {%8,%9}, {%0,%1,%2,%3};" \
        : "+f"((dd)[0]), "+f"((dd)[1]), "+f"((dd)[2]), "+f"((dd)[3]) \
        : "r"((aa)[0]), "r"((aa)[1]), "r"((aa)[2]), "r"((aa)[3]), "r"(b0), "r"(b1))

#define CP_ASYNC16(sa, ga) \
    asm volatile("cp.async.cg.shared.global [%0], [%1], 16;" :: "r"(sa), "l"(ga) : "memory")

// ---------------- meta (all 4 offsets) ----------------
__global__ void meta_kernel(const float* __restrict__ coord) {
    int m = blockIdx.x * blockDim.x + threadIdx.x;
    if (m >= MTOT) return;
    float cy0 = coord[2 * m + 0];
    float cx0 = coord[2 * m + 1];
    {
        float fy = (cy0 + 1.0f) * 128.0f - 0.5f;
        float fx = (cx0 + 1.0f) * 128.0f - 0.5f;
        int iy = (int)floorf(fy + 0.5f);
        int ix = (int)floorf(fx + 0.5f);
        bool v = (iy >= 0) && (iy < 256) && (ix >= 0) && (ix < 256);
        int iyc = min(max(iy, 0), 255);
        int ixc = min(max(ix, 0), 255);
        g_ihr[m] = v ? (iyc * 256 + ixc) : -1;
    }
#pragma unroll
    for (int o = 0; o < 4; o++) {
        float vx = (o < 2) ? -1.0f : 1.0f;
        float vy = (o & 1) ? 1.0f : -1.0f;
        float cy = cy0 + vx * (1.0f / 64.0f);
        float cx = cx0 + vy * (1.0f / 64.0f);
        float fy = (cy + 1.0f) * 32.0f - 0.5f;
        float fx = (cx + 1.0f) * 32.0f - 0.5f;
        int iy = (int)floorf(fy + 0.5f);
        int ix = (int)floorf(fx + 0.5f);
        bool v = (iy >= 0) && (iy < 64) && (ix >= 0) && (ix < 64);
        int iyc = min(max(iy, 0), 63);
        int ixc = min(max(ix, 0), 63);
        g_ilr4[o * MTOT + m] = v ? (iyc * 64 + ixc) : -1;
        const float rh = 1.0f / 64.0f;
        float qy = v ? (-1.0f + rh + 2.0f * rh * (float)iyc) : 0.0f;
        float qx = v ? (-1.0f + rh + 2.0f * rh * (float)ixc) : 0.0f;
        g_rely4[o * MTOT + m] = (cy0 - qy) * 64.0f;
        g_relx4[o * MTOT + m] = (cx0 - qx) * 64.0f;
    }
}

// ---------------- weight prep ----------------
// layers 2..4: single fp16 W [n][Kpad]
__global__ void prep_w_kernel(const float* __restrict__ W, int layer) {
    __half* Wd;
    int Kpad, N;
    switch (layer) {
        case 2: Wd = g_W2; Kpad = KP2; N = NO2; break;
        case 3: Wd = g_W3; Kpad = KP3; N = NO3; break;
        default:Wd = g_W4; Kpad = KP4; N = NO4; break;
    }
    size_t idx = (size_t)blockIdx.x * blockDim.x + threadIdx.x;
    if (idx >= (size_t)N * Kpad) return;
    int n = (int)(idx / Kpad);
    int k = (int)(idx % Kpad);
    Wd[idx] = __float2half_rn(W[(size_t)k * N + n]);
}

__global__ void prep_whr_kernel(const float* __restrict__ w1) {
    size_t idx = (size_t)blockIdx.x * blockDim.x + threadIdx.x;
    if (idx >= (size_t)NO1 * KH) return;
    int n = (int)(idx / KH);
    int k = (int)(idx % KH);
    float v = w1[(size_t)(128 + k) * NO1 + n] + w1[(size_t)(256 + k) * NO1 + n];
    __half h, l;
    f16_split(v, h, l);
    g_WHRh[idx] = h;
    g_WHRl[idx] = l;
}

__global__ void prep_wcell_kernel(const float* __restrict__ w1) {
    size_t idx = (size_t)blockIdx.x * blockDim.x + threadIdx.x;
    if (idx >= (size_t)NO1 * KC) return;
    int n = (int)(idx / KC);
    int k = (int)(idx % KC);
    float v = (k < 128) ? w1[(size_t)k * NO1 + n]
                        : -w1[(size_t)(128 + k) * NO1 + n];
    __half h, l;
    f16_split(v, h, l);
    g_WCh[idx] = h;
    g_WCl[idx] = l;
}

// ---------------- one-time fills ----------------
__global__ __launch_bounds__(256) void fill_qhr_kernel(const float* __restrict__ hr) {
    __shared__ float vals[KH][33];
    __shared__ int s_ih[32];
    int t = threadIdx.x;
    int m0 = blockIdx.x * 32;
    if (t < 32) s_ih[t] = g_ihr[m0 + t];
    __syncthreads();
    int ml = t & 31;
    int cb = t >> 5;
    int b = (m0 + ml) >> 16;
    int ih = s_ih[ml];
#pragma unroll 4
    for (int cc = 0; cc < KH; cc += 8) {
        int c = cc + cb;
        vals[c][ml] = (ih >= 0) ? hr[(size_t)(b * 128 + c) * 65536 + ih] : 0.0f;
    }
    __syncthreads();
    int mw = t >> 3;
    int kb = (t & 7) * 16;
    size_t base = (size_t)(m0 + mw) * KH;
#pragma unroll
    for (int kk = 0; kk < 16; kk += 2) {
        int k = kb + kk;
        __half h0, l0, h1, l1;
        f16_split(vals[k][mw], h0, l0);
        f16_split(vals[k + 1][mw], h1, l1);
        *(__half2*)(P_QHRh + base + k) = __halves2half2(h0, h1);
        *(__half2*)(P_QHRl + base + k) = __halves2half2(l0, l1);
    }
}

__global__ void fill_cell_kernel(const float* __restrict__ feat,
                                 const float* __restrict__ lr) {
    size_t idx = (size_t)blockIdx.x * blockDim.x + threadIdx.x;
    if (idx >= (size_t)NCELL * KC) return;
    int k  = (int)(idx >> 13);
    int cr = (int)(idx & 8191);
    int b = cr >> 12;
    int cell = cr & 4095;
    float v = (k < 128) ? feat[(size_t)(b * 128 + k) * 4096 + cell]
                        : lr[(size_t)(b * 128 + (k - 128)) * 4096 + cell];
    __half h, l;
    f16_split(v, h, l);
    P_CELLh[(size_t)cr * KC + k] = h;
    P_CELLl[(size_t)cr * KC + k] = l;
}

// ---------------- mma.sync GEMM (3-stage pipeline) ----------------
// 2-term layers (2-4): out = (Ahi+Alo) @ W, W single fp16.
// 3-term layers (0,1): out = Ahi@Wh + Ahi@Wl + Alo@Wh.
#define TILE_BYTES 16384
#define STAGE_BYTES (4 * TILE_BYTES)
#define NSTAGE 3
#define GEMM_SMEM   (NSTAGE * STAGE_BYTES + 1024)

__global__ __launch_bounds__(256) void gemm_mma(int layer, const float* __restrict__ bias) {
    const __half *Ah, *Al, *Wh, *Wl = nullptr;
    __half *Oh = nullptr, *Ol = nullptr;
    float* Of = nullptr;
    int Kpad, Nout, fuse, terms;
    switch (layer) {
        case 0: Ah = P_QHRh;  Al = P_QHRl;  Wh = g_WHRh; Wl = g_WHRl; Of = P_YHR; Kpad = KH;  Nout = NO1; fuse = 0; terms = 3; break;
        case 1: Ah = P_CELLh; Al = P_CELLl; Wh = g_WCh;  Wl = g_WCl;  Of = g_Z;   Kpad = KC;  Nout = NO1; fuse = 0; terms = 3; break;
        case 2: Ah = P_X1h;   Al = P_X1l;   Wh = g_W2;   Oh = P_X2h;  Ol = P_X2l; Kpad = KP2; Nout = NO2; fuse = 1; terms = 2; break;
        case 3: Ah = P_X2h;   Al = P_X2l;   Wh = g_W3;   Oh = P_X3h;  Ol = P_X3l; Kpad = KP3; Nout = NO3; fuse = 1; terms = 2; break;
        default:Ah = P_X3h;   Al = P_X3l;   Wh = g_W4;   Oh = P_X4h;  Ol = P_X4l; Kpad = KP4; Nout = NO4; fuse = 1; terms = 2; break;
    }

    extern __shared__ char dsm[];
    __shared__ float s_bias[128];

    int tid = threadIdx.x;
    int wid = tid >> 5;
    int lane = tid & 31;
    int warp_m = wid >> 2;
    int warp_n = wid & 3;
    int n0 = blockIdx.x * 128;
    int m0 = blockIdx.y * 128;

    uint32_t dyn = (smem_u32(dsm) + 1023u) & ~1023u;
    if (fuse && tid < 128) s_bias[tid] = bias[n0 + tid];

    const int NC = Kpad >> 6;

    float acc[4][4][4];
#pragma unroll
    for (int i = 0; i < 4; i++)
#pragma unroll
        for (int j = 0; j < 4; j++)
#pragma unroll
            for (int r = 0; r < 4; r++) acc[i][j][r] = 0.0f;

    uint32_t a_off[4], a_xor[4];
#pragma unroll
    for (int i = 0; i < 4; i++) {
        uint32_t row = warp_m * 64 + i * 16 + (lane & 15);
        a_off[i] = row << 7;
        a_xor[i] = (row & 7) << 4;
    }
    uint32_t w_off[2], w_xor[2];
#pragma unroll
    for (int j2 = 0; j2 < 2; j2++) {
        uint32_t row = warp_n * 32 + j2 * 16 + ((lane >> 4) << 3) + (lane & 7);
        w_off[j2] = row << 7;
        w_xor[j2] = (row & 7) << 4;
    }
    uint32_t a_hi16 = (lane >> 4) << 4;
    uint32_t w_hi16 = ((lane >> 3) & 1) << 4;

    // tiles per stage: 0=Ahi, 1=Alo, 2=Wh, 3=Wl (terms==3 only)
    auto issue_loads = [&](int c) {
        uint32_t sb = dyn + (c % NSTAGE) * STAGE_BYTES;
        int k0 = c << 6;
#pragma unroll
        for (int it = 0; it < 12; it++) {
            int tile = it >> 2;
            int c2 = ((it & 3) << 8) + tid;
            int row = c2 >> 3;
            int col = c2 & 7;
            const __half* src;
            size_t gidx;
            if (tile < 2) {
                src = (tile == 0) ? Ah : Al;
                gidx = (size_t)(m0 + row) * Kpad + k0 + col * 8;
            } else {
                src = Wh;
                gidx = (size_t)(n0 + row) * Kpad + k0 + col * 8;
            }
            uint32_t sa = sb + tile * TILE_BYTES + swz128((row << 7) + (col << 4));
            CP_ASYNC16(sa, __cvta_generic_to_global(src + gidx));
        }
        if (terms == 3) {
#pragma unroll
            for (int it = 0; it < 4; it++) {
                int c2 = (it << 8) + tid;
                int row = c2 >> 3;
                int col = c2 & 7;
                size_t gidx = (size_t)(n0 + row) * Kpad + k0 + col * 8;
                uint32_t sa = sb + 3 * TILE_BYTES + swz128((row << 7) + (col << 4));
                CP_ASYNC16(sa, __cvta_generic_to_global(Wl + gidx));
            }
        }
    };

    issue_loads(0);
    asm volatile("cp.async.commit_group;" ::: "memory");
    if (NC > 1) issue_loads(1);
    asm volatile("cp.async.commit_group;" ::: "memory");

    for (int c = 0; c < NC; c++) {
        asm volatile("cp.async.wait_group %0;" :: "n"(NSTAGE - 2) : "memory");
        __syncthreads();

        if (c + NSTAGE - 1 < NC) issue_loads(c + NSTAGE - 1);
        asm volatile("cp.async.commit_group;" ::: "memory");

        uint32_t sb  = dyn + (c % NSTAGE) * STAGE_BYTES;
        uint32_t bAh = sb;
        uint32_t bAl = sb + TILE_BYTES;
        uint32_t bWh = sb + 2 * TILE_BYTES;
        uint32_t bWl = sb + 3 * TILE_BYTES;

#pragma unroll
        for (int ks = 0; ks < 4; ks++) {
            uint32_t bcA = (uint32_t)(ks * 32) + a_hi16;
            uint32_t bcW = (uint32_t)(ks * 32) + w_hi16;
            uint32_t ahi[4][4], alo[4][4];
#pragma unroll
            for (int i = 0; i < 4; i++) {
                uint32_t o = a_off[i] + (bcA ^ a_xor[i]);
                LDSM4(ahi[i], bAh + o);
                LDSM4(alo[i], bAl + o);
            }
            uint32_t bhi[2][4];
#pragma unroll
            for (int j2 = 0; j2 < 2; j2++) {
                uint32_t o = w_off[j2] + (bcW ^ w_xor[j2]);
                LDSM4(bhi[j2], bWh + o);
            }
            // 16 independent MMAs per term group (no RAW chains)
#pragma unroll
            for (int i = 0; i < 4; i++)
#pragma unroll
                for (int j = 0; j < 4; j++) {
                    int j2 = j >> 1, jh = (j & 1) << 1;
                    MMA_F16(acc[i][j], ahi[i], bhi[j2][jh], bhi[j2][jh + 1]);
                }
#pragma unroll
            for (int i = 0; i < 4; i++)
#pragma unroll
                for (int j = 0; j < 4; j++) {
                    int j2 = j >> 1, jh = (j & 1) << 1;
                    MMA_F16(acc[i][j], alo[i], bhi[j2][jh], bhi[j2][jh + 1]);
                }
            if (terms == 3) {
                uint32_t blo[2][4];
#pragma unroll
                for (int j2 = 0; j2 < 2; j2++) {
                    uint32_t o = w_off[j2] + (bcW ^ w_xor[j2]);
                    LDSM4(blo[j2], bWl + o);
                }
#pragma unroll
                for (int i = 0; i < 4; i++)
#pragma unroll
                    for (int j = 0; j < 4; j++) {
                        int j2 = j >> 1, jh = (j & 1) << 1;
                        MMA_F16(acc[i][j], ahi[i], blo[j2][jh], blo[j2][jh + 1]);
                    }
            }
        }
    }

    int q = lane >> 2, p = lane & 3;
#pragma unroll
    for (int i = 0; i < 4; i++) {
        int r0 = m0 + warp_m * 64 + i * 16 + q;
        size_t o0 = (size_t)r0 * Nout + n0;
        size_t o1 = (size_t)(r0 + 8) * Nout + n0;
#pragma unroll
        for (int j = 0; j < 4; j++) {
            int nn = warp_n * 32 + j * 8 + p * 2;
            if (fuse) {
                float bb0 = s_bias[nn], bb1 = s_bias[nn + 1];
                float v00 = fmaxf(acc[i][j][0] + bb0, 0.0f);
                float v01 = fmaxf(acc[i][j][1] + bb1, 0.0f);
                float v10 = fmaxf(acc[i][j][2] + bb0, 0.0f);
                float v11 = fmaxf(acc[i][j][3] + bb1, 0.0f);
                __half h00, l00, h01, l01, h10, l10, h11, l11;
                f16_split(v00, h00, l00);
                f16_split(v01, h01, l01);
                f16_split(v10, h10, l10);
                f16_split(v11, h11, l11);
                *(__half2*)(Oh + o0 + nn) = __halves2half2(h00, h01);
                *(__half2*)(Ol + o0 + nn) = __halves2half2(l00, l01);
                *(__half2*)(Oh + o1 + nn) = __halves2half2(h10, h11);
                *(__half2*)(Ol + o1 + nn) = __halves2half2(l10, l11);
            } else {
                *(float2*)(Of + o0 + nn) = make_float2(acc[i][j][0], acc[i][j][1]);
                *(float2*)(Of + o1 + nn) = make_float2(acc[i][j][2], acc[i][j][3]);
            }
        }
    }
}

// ---------------- fused layer-1 assembly for ALL 4 offsets ----------------
__global__ __launch_bounds__(256) void assemble_all_kernel(const float* __restrict__ w1,
                                                           const float* __restrict__ b1) {
    __shared__ float s_wd0[NO1], s_wd1[NO1], s_b1[NO1];
    __shared__ int   s_il[4][8];
    __shared__ float s_ry[4][8], s_rx[4][8];
    int t = threadIdx.x;
    int m0 = blockIdx.x * 8;
#pragma unroll
    for (int i = t; i < NO1; i += 256) {
        s_wd0[i] = w1[(size_t)384 * NO1 + i];
        s_wd1[i] = w1[(size_t)385 * NO1 + i];
        s_b1[i]  = b1[i];
    }
    if (t < 32) {
        int o = t >> 3, pi = t & 7;
        int m = m0 + pi;
        s_il[o][pi] = g_ilr4[o * MTOT + m];
        s_ry[o][pi] = g_rely4[o * MTOT + m];
        s_rx[o][pi] = g_relx4[o * MTOT + m];
    }
    __syncthreads();

    for (int pi = 0; pi < 8; pi++) {
        int m = m0 + pi;
        int b = m >> 16;
        size_t ybase = (size_t)m << 10;
#pragma unroll
        for (int it = 0; it < 2; it++) {
            int n = it * 512 + t * 2;
            float2 y = *(const float2*)(P_YHR + ybase + n);
            float wd0a = s_wd0[n], wd0b = s_wd0[n + 1];
            float wd1a = s_wd1[n], wd1b = s_wd1[n + 1];
            float ba = s_b1[n], bb = s_b1[n + 1];
#pragma unroll
            for (int o = 0; o < 4; o++) {
                int il = s_il[o][pi];
                float z0 = 0.0f, z1 = 0.0f;
                if (il >= 0) {
                    float2 z = *(const float2*)(g_Z + (((size_t)(b * 4096 + il)) << 10) + n);
                    z0 = z.x; z1 = z.y;
                }
                float ry = s_ry[o][pi], rxx = s_rx[o][pi];
                float v0 = fmaxf(y.x + z0 + ry * wd0a + rxx * wd1a + ba, 0.0f);
                float v1 = fmaxf(y.y + z1 + ry * wd0b + rxx * wd1b + bb, 0.0f);
                __half h0, l0, h1, l1;
                f16_split(v0, h0, l0);
                f16_split(v1, h1, l1);
                size_t obase = ((size_t)(o * MTOT + m) << 10) + n;
                *(__half2*)(P_X1h + obase) = __halves2half2(h0, h1);
                *(__half2*)(P_X1l + obase) = __halves2half2(l0, l1);
            }
        }
    }
}

// ---------------- layer 5 (merged M = 524288) ----------------
__global__ __launch_bounds__(256) void layer5_kernel(const float* __restrict__ w5,
                                                     const float* __restrict__ b5) {
    __shared__ float ws0[128], ws1[128];
    int t = threadIdx.x;
    if (t < 128) {
        ws0[t] = w5[t * 2 + 0];
        ws1[t] = w5[t * 2 + 1];
    }
    __syncthreads();
    int m = blockIdx.x * 8 + (t >> 5);
    int lane = t & 31;
    size_t base = (size_t)m * 128 + lane * 4;
    __half2 h01 = *(const __half2*)(P_X4h + base);
    __half2 h23 = *(const __half2*)(P_X4h + base + 2);
    __half2 l01 = *(const __half2*)(P_X4l + base);
    __half2 l23 = *(const __half2*)(P_X4l + base + 2);
    float x0 = __half2float(h01.x) + __half2float(l01.x);
    float x1 = __half2float(h01.y) + __half2float(l01.y);
    float x2 = __half2float(h23.x) + __half2float(l23.x);
    float x3 = __half2float(h23.y) + __half2float(l23.y);
    int k = lane * 4;
    float a0 = x0 * ws0[k] + x1 * ws0[k + 1] + x2 * ws0[k + 2] + x3 * ws0[k + 3];
    float a1 = x0 * ws1[k] + x1 * ws1[k + 1] + x2 * ws1[k + 2] + x3 * ws1[k + 3];
#pragma unroll
    for (int s = 16; s > 0; s >>= 1) {
        a0 += __shfl_xor_sync(0xFFFFFFFF, a0, s);
        a1 += __shfl_xor_sync(0xFFFFFFFF, a1, s);
    }
    if (lane == 0) {
        g_P0[m] = a0 + b5[0];
        g_P1[m] = a1 + b5[1];
    }
}

// ---------------- softmax combine ----------------
__global__ void combine_kernel(float* __restrict__ out) {
    int m = blockIdx.x * blockDim.x + threadIdx.x;
    if (m >= MTOT) return;
    float l0 = g_P1[0 * MTOT + m];
    float l1 = g_P1[1 * MTOT + m];
    float l2 = g_P1[2 * MTOT + m];
    float l3 = g_P1[3 * MTOT + m];
    float mx = fmaxf(fmaxf(l0, l1), fmaxf(l2, l3));
    float e0 = expf(l0 - mx), e1 = expf(l1 - mx), e2 = expf(l2 - mx), e3 = expf(l3 - mx);
    float s = e0 + e1 + e2 + e3;
    float r = (g_P0[0 * MTOT + m] * e0 + g_P0[1 * MTOT + m] * e1 +
               g_P0[2 * MTOT + m] * e2 + g_P0[3 * MTOT + m] * e3) / s;
    out[m] = r;
}

extern "C" void kernel_launch(void* const* d_in, const int* in_sizes, int n_in,
                              void* d_out, int out_size) {
    const float* feat  = (const float*)d_in[0];
    const float* coord = (const float*)d_in[1];
    const float* hr    = (const float*)d_in[2];
    const float* lr    = (const float*)d_in[3];
    const float* w1 = (const float*)d_in[4];  const float* b1 = (const float*)d_in[5];
    const float* w2 = (const float*)d_in[6];  const float* b2 = (const float*)d_in[7];
    const float* w3 = (const float*)d_in[8];  const float* b3 = (const float*)d_in[9];
    const float* w4 = (const float*)d_in[10]; const float* b4 = (const float*)d_in[11];
    const float* w5 = (const float*)d_in[12]; const float* b5 = (const float*)d_in[13];
    float* out = (float*)d_out;

    cudaFuncSetAttribute(gemm_mma, cudaFuncAttributeMaxDynamicSharedMemorySize, GEMM_SMEM);

    // weight prep
    prep_whr_kernel<<<(unsigned)(((size_t)NO1 * KH + 255) / 256), 256>>>(w1);
    prep_wcell_kernel<<<(unsigned)(((size_t)NO1 * KC + 255) / 256), 256>>>(w1);
    prep_w_kernel<<<(unsigned)(((size_t)NO2 * KP2 + 255) / 256), 256>>>(w2, 2);
    prep_w_kernel<<<(unsigned)(((size_t)NO3 * KP3 + 255) / 256), 256>>>(w3, 3);
    prep_w_kernel<<<(unsigned)(((size_t)NO4 * KP4 + 255) / 256), 256>>>(w4, 4);

    // offset-independent precompute
    meta_kernel<<<MTOT / 256, 256>>>(coord);
    fill_qhr_kernel<<<MTOT / 32, 256>>>(hr);
    fill_cell_kernel<<<(unsigned)(((size_t)NCELL * KC + 255) / 256), 256>>>(feat, lr);
    gemm_mma<<<dim3(NO1 / 128, MTOT / 128), 256, GEMM_SMEM>>>(0, nullptr);   // YHR
    gemm_mma<<<dim3(NO1 / 128, NCELL / 128), 256, GEMM_SMEM>>>(1, nullptr);  // Z

    // merged 4-offset batch
    assemble_all_kernel<<<MTOT / 8, 256>>>(w1, b1);
    gemm_mma<<<dim3(NO2 / 128, MT4 / 128), 256, GEMM_SMEM>>>(2, b2);
    gemm_mma<<<dim3(NO3 / 128, MT4 / 128), 256, GEMM_SMEM>>>(3, b3);
    gemm_mma<<<dim3(NO4 / 128, MT4 / 128), 256, GEMM_SMEM>>>(4, b4);
    layer5_kernel<<<MT4 / 8, 256>>>(w5, b5);
    combine_kernel<<<MTOT / 256, 256>>>(out);
}